// round 11
// baseline (speedup 1.0000x reference)
#include <cuda_runtime.h>
#include <math_constants.h>
#include <cstdint>

// Problem constants
#define BB   8
#define CC   256
#define CR   128
#define TT   16
#define HWD  784            // 28*28
#define THW  12544          // 16*784
#define KTOP 196            // 784/4
#define NROW 1024           // B*CR
#define BN_EPS 1e-5f

// Scratch buffers
__device__ float g_Q [BB * CR * THW];
__device__ float g_K [BB * CR * THW];
__device__ float g_V [BB * CR * THW];
__device__ float g_Qt[NROW * TT * KTOP];
__device__ float g_Kt[NROW * TT * KTOP];
__device__ float g_Y [BB * CR * THW];
// Pre-converted (tf32-bit) weights
__device__ float g_Wqt[CR * CC];
__device__ float g_Wkt[CR * CC];
__device__ float g_Wvt[CR * CC];
__device__ float g_Wrt[CC * CR];

__device__ __forceinline__ uint32_t f2tf32(float x) {
    uint32_t u;
    asm("cvt.rna.tf32.f32 %0, %1;" : "=r"(u) : "f"(x));
    return u;
}
__device__ __forceinline__ void cpasync16(uint32_t daddr, const void* src) {
    asm volatile("cp.async.ca.shared.global [%0], [%1], 16;\n"
                 :: "r"(daddr), "l"(src));
}

// ---------------------------------------------------------------------------
// Weight tf32 preconversion
// ---------------------------------------------------------------------------
__global__ __launch_bounds__(256) void wconv_kernel(
    const float* __restrict__ w0, const float* __restrict__ w1,
    const float* __restrict__ w2, const float* __restrict__ w3,
    float* __restrict__ d0, float* __restrict__ d1,
    float* __restrict__ d2, float* __restrict__ d3)
{
    const int a = blockIdx.y;
    const float* s = (a == 0) ? w0 : (a == 1) ? w1 : (a == 2) ? w2 : w3;
    float*       d = (a == 0) ? d0 : (a == 1) ? d1 : (a == 2) ? d2 : d3;
    int i = blockIdx.x * 256 + threadIdx.x;
    d[i] = __uint_as_float(f2tf32(s[i]));
}

// ---------------------------------------------------------------------------
// Pipelined tf32 GEMM, 2-stage cp.async, 512 threads (16 warps, 4Mx4N).
// ---------------------------------------------------------------------------
#define TBM 128
#define TBN 128
#define TBK 16
#define APAD 20
#define BPAD 136

template<int CVTB>
__global__ __launch_bounds__(512) void gemm_tf32_pipe_kernel(
    const float* __restrict__ A0, const float* __restrict__ A1,
    const float* __restrict__ A2,
    const float* __restrict__ Bmat,
    float* __restrict__ C0, float* __restrict__ C1, float* __restrict__ C2,
    const float* __restrict__ bias0, const float* __restrict__ bias1,
    const float* __restrict__ bias2,
    const float* __restrict__ gamma,
    const float* __restrict__ beta,
    const float* __restrict__ bn_mean,
    const float* __restrict__ bn_var,
    const float* __restrict__ xres,
    int M, int K, int mode)
{
    const int b    = blockIdx.z;
    const int bx   = blockIdx.x;
    const int n0   = blockIdx.y * TBN;
    const int tid  = threadIdx.x;
    const int lane = tid & 31;
    const int wid  = tid >> 5;
    const int wm   = wid >> 2;
    const int wn   = wid & 3;

    const float* A;
    const float* bias;
    float* C;
    int m0;
    if (mode == 0) {
        A    = (bx == 0) ? A0 : (bx == 1) ? A1 : A2;
        bias = (bx == 0) ? bias0 : (bx == 1) ? bias1 : bias2;
        C    = (bx == 0) ? C0 : (bx == 1) ? C1 : C2;
        m0   = 0;
    } else {
        A = A0; bias = bias0; C = C0;
        m0 = bx * TBM;
    }

    const float* Bb = Bmat + (size_t)b * K * THW;
    float*       Cb = C    + (size_t)b * M * THW;

    __shared__ float As[2][TBM][APAD];
    __shared__ float Bs[2][TBK][BPAD];

    float acc[2][4][4];
#pragma unroll
    for (int i = 0; i < 2; i++)
#pragma unroll
        for (int j = 0; j < 4; j++)
#pragma unroll
            for (int q = 0; q < 4; q++) acc[i][j][q] = 0.f;

    const int row = lane >> 2;
    const int kc  = lane & 3;

    const int am = tid >> 2, ak = tid & 3;
    const int bk = tid >> 5, bn = tid & 31;

    uint32_t asBase = (uint32_t)__cvta_generic_to_shared(&As[0][0][0]);
    uint32_t bsBase = (uint32_t)__cvta_generic_to_shared(&Bs[0][0][0]);
    const uint32_t asStage = TBM * APAD * 4;
    const uint32_t bsStage = TBK * BPAD * 4;

    const int nkt = K / TBK;

    cpasync16(asBase + (am * APAD + ak * 4) * 4,
              A + (size_t)(m0 + am) * K + ak * 4);
    cpasync16(bsBase + (bk * BPAD + bn * 4) * 4,
              Bb + (size_t)bk * THW + n0 + bn * 4);
    asm volatile("cp.async.commit_group;\n");

    for (int i = 0; i < nkt; i++) {
        const int s = i & 1;
        if (i + 1 < nkt) {
            const int kt = (i + 1) * TBK;
            const uint32_t so = (s ^ 1);
            cpasync16(asBase + so * asStage + (am * APAD + ak * 4) * 4,
                      A + (size_t)(m0 + am) * K + kt + ak * 4);
            cpasync16(bsBase + so * bsStage + (bk * BPAD + bn * 4) * 4,
                      Bb + (size_t)(kt + bk) * THW + n0 + bn * 4);
            asm volatile("cp.async.commit_group;\n");
            asm volatile("cp.async.wait_group 1;\n");
        } else {
            asm volatile("cp.async.wait_group 0;\n");
        }
        __syncthreads();

#pragma unroll
        for (int ks = 0; ks < 2; ks++) {
            const int kb = ks * 8;
            uint32_t af[2][4];
#pragma unroll
            for (int mt = 0; mt < 2; mt++) {
                int mr = wm * 32 + mt * 16 + row;
                af[mt][0] = __float_as_uint(As[s][mr    ][kb + kc    ]);
                af[mt][1] = __float_as_uint(As[s][mr + 8][kb + kc    ]);
                af[mt][2] = __float_as_uint(As[s][mr    ][kb + kc + 4]);
                af[mt][3] = __float_as_uint(As[s][mr + 8][kb + kc + 4]);
            }
            uint32_t bf[4][2];
#pragma unroll
            for (int nt = 0; nt < 4; nt++) {
                int nc = wn * 32 + nt * 8 + row;
                if (CVTB) {
                    bf[nt][0] = f2tf32(Bs[s][kb + kc    ][nc]);
                    bf[nt][1] = f2tf32(Bs[s][kb + kc + 4][nc]);
                } else {
                    bf[nt][0] = __float_as_uint(Bs[s][kb + kc    ][nc]);
                    bf[nt][1] = __float_as_uint(Bs[s][kb + kc + 4][nc]);
                }
            }
#pragma unroll
            for (int mt = 0; mt < 2; mt++)
#pragma unroll
                for (int nt = 0; nt < 4; nt++) {
                    asm volatile(
                        "mma.sync.aligned.m16n8k8.row.col.f32.tf32.tf32.f32 "
                        "{%0,%1,%2,%3}, {%4,%5,%6,%7}, {%8,%9}, {%0,%1,%2,%3};"
                        : "+f"(acc[mt][nt][0]), "+f"(acc[mt][nt][1]),
                          "+f"(acc[mt][nt][2]), "+f"(acc[mt][nt][3])
                        : "r"(af[mt][0]), "r"(af[mt][1]),
                          "r"(af[mt][2]), "r"(af[mt][3]),
                          "r"(bf[nt][0]), "r"(bf[nt][1]));
                }
        }
        __syncthreads();
    }

    const int coln = 2 * (lane & 3);
#pragma unroll
    for (int mt = 0; mt < 2; mt++) {
#pragma unroll
        for (int half = 0; half < 2; half++) {
            int m = m0 + wm * 32 + mt * 16 + row + half * 8;
            float bi = bias[m];
            float sc = 1.f, sh = 0.f;
            if (mode == 1) {
                sc = gamma[m] * rsqrtf(bn_var[m] + BN_EPS);
                sh = beta[m] - bn_mean[m] * sc;
            }
#pragma unroll
            for (int nt = 0; nt < 4; nt++) {
                int n = n0 + wn * 32 + nt * 8 + coln;
                float v0 = acc[mt][nt][half * 2 + 0] + bi;
                float v1 = acc[mt][nt][half * 2 + 1] + bi;
                if (mode == 1) {
                    const float* xr = xres + (size_t)b * CC * THW + (size_t)m * THW + n;
                    v0 = v0 * sc + sh + xr[0];
                    v1 = v1 * sc + sh + xr[1];
                }
                *reinterpret_cast<float2*>(&Cb[(size_t)m * THW + n]) =
                    make_float2(v0, v1);
            }
        }
    }
}

// ---------------------------------------------------------------------------
// Pruned warp top-k (unchanged — known good)
// ---------------------------------------------------------------------------
template<int J>
__device__ __forceinline__ void shflStepRT(float* v, bool tm) {
#pragma unroll
    for (int r = 0; r < 32; r++) {
        float p  = __shfl_xor_sync(0xffffffffu, v[r], J);
        float mn = fminf(v[r], p), mx = fmaxf(v[r], p);
        v[r] = tm ? mx : mn;
    }
}
template<int J, int KR>
__device__ __forceinline__ void shflStepCT(float* v, bool loJ) {
#pragma unroll
    for (int r = 0; r < 32; r++) {
        const bool tm = ((r & KR) == 0) ? true : false;
        float p  = __shfl_xor_sync(0xffffffffu, v[r], J);
        float mn = fminf(v[r], p), mx = fmaxf(v[r], p);
        v[r] = (tm ? loJ : !loJ) ? mx : mn;
    }
}
template<int JR, int KR>
__device__ __forceinline__ void regStep(float* v) {
#pragma unroll
    for (int r = 0; r < 32; r++) if (!(r & JR)) {
        float a = v[r], b = v[r | JR];
        if ((r & KR) == 0) { v[r] = fmaxf(a, b); v[r | JR] = fminf(a, b); }
        else               { v[r] = fminf(a, b); v[r | JR] = fmaxf(a, b); }
    }
}
template<int KR>
__device__ __forceinline__ void shflSweepCT(float* v, bool lo16, bool lo8,
                                            bool lo4, bool lo2, bool lo1) {
    shflStepCT<16, KR>(v, lo16);
    shflStepCT<8,  KR>(v, lo8);
    shflStepCT<4,  KR>(v, lo4);
    shflStepCT<2,  KR>(v, lo2);
    shflStepCT<1,  KR>(v, lo1);
}
template<int JR>
__device__ __forceinline__ void mergeStepDual(float* v) {
#pragma unroll
    for (int q = 0; q < 8; q++) if (!(q & JR)) {
        { float a = v[q], b = v[q | JR];
          v[q] = fmaxf(a, b); v[q | JR] = fminf(a, b); }
        { float a = v[16 + q], b = v[16 + (q | JR)];
          v[16 + q] = fminf(a, b); v[16 + (q | JR)] = fmaxf(a, b); }
    }
}
template<int J>
__device__ __forceinline__ void shflMergeDual(float* v, bool loJ) {
#pragma unroll
    for (int q = 0; q < 8; q++) {
        { float p = __shfl_xor_sync(0xffffffffu, v[q], J);
          float mn = fminf(v[q], p), mx = fmaxf(v[q], p);
          v[q] = loJ ? mx : mn; }
        { float p = __shfl_xor_sync(0xffffffffu, v[16 + q], J);
          float mn = fminf(v[16 + q], p), mx = fmaxf(v[16 + q], p);
          v[16 + q] = loJ ? mn : mx; }
    }
}
template<int JR>
__device__ __forceinline__ void mergeStepFinal(float* v) {
#pragma unroll
    for (int q = 0; q < 8; q++) if (!(q & JR)) {
        float a = v[q], b = v[q | JR];
        v[q] = fmaxf(a, b); v[q | JR] = fminf(a, b);
    }
}
template<int J>
__device__ __forceinline__ void shflFinal(float* v, bool loJ) {
#pragma unroll
    for (int q = 0; q < 8; q++) {
        float p  = __shfl_xor_sync(0xffffffffu, v[q], J);
        float mn = fminf(v[q], p), mx = fmaxf(v[q], p);
        v[q] = loJ ? mx : mn;
    }
}

__global__ __launch_bounds__(256) void topk_warp_kernel(
    const float* __restrict__ srcQ, float* __restrict__ dstQ,
    const float* __restrict__ srcK, float* __restrict__ dstK, int nrows)
{
    const int lane = threadIdx.x & 31;
    const int row  = blockIdx.x * (blockDim.x >> 5) + (threadIdx.x >> 5);
    if (row >= nrows) return;

    const float* src = blockIdx.y ? srcK : srcQ;
    float*       dst = blockIdx.y ? dstK : dstQ;

    const float* rp = src + (size_t)row * HWD;
    float v[32];
#pragma unroll
    for (int r = 0; r < 24; r++) v[r] = rp[r * 32 + lane];
    v[24] = (lane < 16) ? rp[24 * 32 + lane] : -CUDART_INF_F;
#pragma unroll
    for (int r = 25; r < 32; r++) v[r] = -CUDART_INF_F;

    const bool lo1  = (lane & 1)  == 0;
    const bool lo2  = (lane & 2)  == 0;
    const bool lo4  = (lane & 4)  == 0;
    const bool lo8  = (lane & 8)  == 0;
    const bool lo16 = (lane & 16) == 0;

    shflStepRT<1>(v, lo2 == lo1);
    shflStepRT<2>(v, lo4 == lo2);
    shflStepRT<1>(v, lo4 == lo1);
    shflStepRT<4>(v, lo8 == lo4);
    shflStepRT<2>(v, lo8 == lo2);
    shflStepRT<1>(v, lo8 == lo1);
    shflStepRT<8>(v, lo16 == lo8);
    shflStepRT<4>(v, lo16 == lo4);
    shflStepRT<2>(v, lo16 == lo2);
    shflStepRT<1>(v, lo16 == lo1);

    shflSweepCT<1>(v, lo16, lo8, lo4, lo2, lo1);
    regStep<1, 2>(v);
    shflSweepCT<2>(v, lo16, lo8, lo4, lo2, lo1);
    regStep<2, 4>(v); regStep<1, 4>(v);
    shflSweepCT<4>(v, lo16, lo8, lo4, lo2, lo1);
    regStep<4, 8>(v); regStep<2, 8>(v); regStep<1, 8>(v);
    shflSweepCT<8>(v, lo16, lo8, lo4, lo2, lo1);

#pragma unroll
    for (int q = 0; q < 8; q++) {
        { float a = v[q],      b = v[q + 8];
          v[q]      = fmaxf(a, b); v[q + 8]  = fminf(a, b); }
        { float a = v[16 + q], b = v[24 + q];
          v[16 + q] = fmaxf(a, b); v[24 + q] = fminf(a, b); }
    }
    mergeStepDual<4>(v); mergeStepDual<2>(v); mergeStepDual<1>(v);
    shflMergeDual<16>(v, lo16); shflMergeDual<8>(v, lo8);
    shflMergeDual<4>(v, lo4);   shflMergeDual<2>(v, lo2);
    shflMergeDual<1>(v, lo1);
#pragma unroll
    for (int q = 0; q < 8; q++) v[q] = fmaxf(v[q], v[16 + q]);
    mergeStepFinal<4>(v); mergeStepFinal<2>(v); mergeStepFinal<1>(v);
    shflFinal<16>(v, lo16); shflFinal<8>(v, lo8);
    shflFinal<4>(v, lo4);   shflFinal<2>(v, lo2);
    shflFinal<1>(v, lo1);

    float* dp = dst + (size_t)row * KTOP;
#pragma unroll
    for (int r = 0; r < 6; r++) dp[r * 32 + lane] = v[r];
    if (lane < 4) dp[6 * 32 + lane] = v[6];
}

// ---------------------------------------------------------------------------
// Attention. grid (n, 2): blockIdx.y selects a 392-wide p-half.
// Low-reg AV loop: v0[16] + 4-acc t-groups, p-loop not unrolled.
// Y pre-rounded to tf32 (bit-identical for rec GEMM).
// ---------------------------------------------------------------------------
__global__ __launch_bounds__(256, 4) void attn_kernel(
    const float* __restrict__ Qt, const float* __restrict__ Kt,
    const float* __restrict__ V, float* __restrict__ Y)
{
    __shared__ float sQ[TT * KTOP];
    __shared__ float sK[TT * KTOP];
    __shared__ float sA[TT * TT];

    const int n   = blockIdx.x;
    const int tid = threadIdx.x;

    const float* qb = Qt + (long)n * TT * KTOP;
    const float* kb = Kt + (long)n * TT * KTOP;
    for (int i = tid; i < TT * KTOP; i += 256) { sQ[i] = qb[i]; sK[i] = kb[i]; }
    __syncthreads();

    {
        int t = tid >> 4, s = tid & 15;
        const float4* q4 = reinterpret_cast<const float4*>(sQ + t * KTOP);
        const float4* k4 = reinterpret_cast<const float4*>(sK + s * KTOP);
        float acc = 0.f;
#pragma unroll 7
        for (int j = 0; j < KTOP / 4; j++) {
            float4 a = q4[j], b = k4[j];
            acc = fmaf(a.x, b.x, acc);
            acc = fmaf(a.y, b.y, acc);
            acc = fmaf(a.z, b.z, acc);
            acc = fmaf(a.w, b.w, acc);
        }
        sA[t * 16 + s] = acc;
    }
    __syncthreads();

    if (tid < TT) {
        int t = tid;
        float mx = -CUDART_INF_F;
#pragma unroll
        for (int s = 0; s < 16; s++) mx = fmaxf(mx, sA[t * 16 + s]);
        float sum = 0.f;
        float e[16];
#pragma unroll
        for (int s = 0; s < 16; s++) { e[s] = __expf(sA[t * 16 + s] - mx); sum += e[s]; }
        float inv = 1.f / sum;
#pragma unroll
        for (int s = 0; s < 16; s++) sA[t * 16 + s] = e[s] * inv;
    }
    __syncthreads();

    const int p0   = blockIdx.y * (HWD / 2);     // 0 or 392
    const int pEnd = p0 + (HWD / 2);
    const float* vb = V + (long)n * THW;
    float* yb = Y + (long)n * THW;

#pragma unroll 1
    for (int p = p0 + tid; p < pEnd; p += 256) {
        float v0[TT];
#pragma unroll
        for (int s = 0; s < TT; s++) v0[s] = vb[s * HWD + p];
#pragma unroll
        for (int tb = 0; tb < 4; tb++) {
            float a0 = 0.f, a1 = 0.f, a2 = 0.f, a3 = 0.f;
#pragma unroll
            for (int s = 0; s < TT; s++) {
                float vv = v0[s];
                a0 = fmaf(sA[(4 * tb + 0) * 16 + s], vv, a0);
                a1 = fmaf(sA[(4 * tb + 1) * 16 + s], vv, a1);
                a2 = fmaf(sA[(4 * tb + 2) * 16 + s], vv, a2);
                a3 = fmaf(sA[(4 * tb + 3) * 16 + s], vv, a3);
            }
            yb[(4 * tb + 0) * HWD + p] = __uint_as_float(f2tf32(a0));
            yb[(4 * tb + 1) * HWD + p] = __uint_as_float(f2tf32(a1));
            yb[(4 * tb + 2) * HWD + p] = __uint_as_float(f2tf32(a2));
            yb[(4 * tb + 3) * HWD + p] = __uint_as_float(f2tf32(a3));
        }
    }
}

// ---------------------------------------------------------------------------
extern "C" void kernel_launch(void* const* d_in, const int* in_sizes, int n_in,
                              void* d_out, int out_size)
{
    const float* x      = (const float*)d_in[0];
    const float* Wq     = (const float*)d_in[1];
    const float* bq     = (const float*)d_in[2];
    const float* Wk     = (const float*)d_in[3];
    const float* bk     = (const float*)d_in[4];
    const float* Wv     = (const float*)d_in[5];
    const float* bv     = (const float*)d_in[6];
    const float* Wr     = (const float*)d_in[7];
    const float* br     = (const float*)d_in[8];
    const float* gamma  = (const float*)d_in[9];
    const float* beta   = (const float*)d_in[10];
    const float* bnmean = (const float*)d_in[11];
    const float* bnvar  = (const float*)d_in[12];
    float* out = (float*)d_out;

    float *Qp, *Kp, *Vp, *Qtp, *Ktp, *Yp, *Wqt, *Wkt, *Wvt, *Wrt;
    cudaGetSymbolAddress((void**)&Qp,  g_Q);
    cudaGetSymbolAddress((void**)&Kp,  g_K);
    cudaGetSymbolAddress((void**)&Vp,  g_V);
    cudaGetSymbolAddress((void**)&Qtp, g_Qt);
    cudaGetSymbolAddress((void**)&Ktp, g_Kt);
    cudaGetSymbolAddress((void**)&Yp,  g_Y);
    cudaGetSymbolAddress((void**)&Wqt, g_Wqt);
    cudaGetSymbolAddress((void**)&Wkt, g_Wkt);
    cudaGetSymbolAddress((void**)&Wvt, g_Wvt);
    cudaGetSymbolAddress((void**)&Wrt, g_Wrt);

    dim3 gW(128, 4);
    wconv_kernel<<<gW, 256>>>(Wq, Wk, Wv, Wr, Wqt, Wkt, Wvt, Wrt);

    dim3 gQKV(3, THW / TBN, BB);             // (3, 98, 8)
    gemm_tf32_pipe_kernel<1><<<gQKV, 512>>>(
        Wqt, Wkt, Wvt, x, Qp, Kp, Vp, bq, bk, bv,
        nullptr, nullptr, nullptr, nullptr, nullptr, CR, CC, 0);

    const int nrows = NROW * TT;             // 16384
    const int wpb = 8;
    dim3 gTK((nrows + wpb - 1) / wpb, 2);
    topk_warp_kernel<<<gTK, 32 * wpb>>>(Qp, Qtp, Kp, Ktp, nrows);

    dim3 gAttn(NROW, 2);
    attn_kernel<<<gAttn, 256>>>(Qtp, Ktp, Vp, Yp);

    dim3 gRec(CC / TBM, THW / TBN, BB);      // (2, 98, 8)
    gemm_tf32_pipe_kernel<0><<<gRec, 512>>>(
        Wrt, nullptr, nullptr, Yp, out, nullptr, nullptr, br, nullptr, nullptr,
        gamma, beta, bnmean, bnvar, x, CC, CR, 1);
}

// round 12
// speedup vs baseline: 1.2268x; 1.2268x over previous
#include <cuda_runtime.h>
#include <math_constants.h>
#include <cstdint>

// Problem constants
#define BB   8
#define CC   256
#define CR   128
#define TT   16
#define HWD  784            // 28*28
#define THW  12544          // 16*784
#define KTOP 196            // 784/4
#define NROW 1024           // B*CR
#define BN_EPS 1e-5f

// Scratch buffers
__device__ float g_Q [BB * CR * THW];
__device__ float g_K [BB * CR * THW];
__device__ float g_V [BB * CR * THW];
__device__ float g_Qt[NROW * TT * KTOP];
__device__ float g_Kt[NROW * TT * KTOP];
__device__ float g_Y [BB * CR * THW];
// Pre-converted (tf32-bit) weights
__device__ float g_Wqt[CR * CC];
__device__ float g_Wkt[CR * CC];
__device__ float g_Wvt[CR * CC];
__device__ float g_Wrt[CC * CR];

__device__ __forceinline__ uint32_t f2tf32(float x) {
    uint32_t u;
    asm("cvt.rna.tf32.f32 %0, %1;" : "=r"(u) : "f"(x));
    return u;
}
__device__ __forceinline__ void cpasync16(uint32_t daddr, const void* src) {
    asm volatile("cp.async.ca.shared.global [%0], [%1], 16;\n"
                 :: "r"(daddr), "l"(src));
}

// ---------------------------------------------------------------------------
// Weight tf32 preconversion
// ---------------------------------------------------------------------------
__global__ __launch_bounds__(256) void wconv_kernel(
    const float* __restrict__ w0, const float* __restrict__ w1,
    const float* __restrict__ w2, const float* __restrict__ w3,
    float* __restrict__ d0, float* __restrict__ d1,
    float* __restrict__ d2, float* __restrict__ d3)
{
    const int a = blockIdx.y;
    const float* s = (a == 0) ? w0 : (a == 1) ? w1 : (a == 2) ? w2 : w3;
    float*       d = (a == 0) ? d0 : (a == 1) ? d1 : (a == 2) ? d2 : d3;
    int i = blockIdx.x * 256 + threadIdx.x;
    d[i] = __uint_as_float(f2tf32(s[i]));
}

// ---------------------------------------------------------------------------
// Pipelined tf32 GEMM, 2-stage cp.async, 512 threads (16 warps, 4Mx4N).
// ---------------------------------------------------------------------------
#define TBM 128
#define TBN 128
#define TBK 16
#define APAD 20
#define BPAD 136

template<int CVTB>
__global__ __launch_bounds__(512) void gemm_tf32_pipe_kernel(
    const float* __restrict__ A0, const float* __restrict__ A1,
    const float* __restrict__ A2,
    const float* __restrict__ Bmat,
    float* __restrict__ C0, float* __restrict__ C1, float* __restrict__ C2,
    const float* __restrict__ bias0, const float* __restrict__ bias1,
    const float* __restrict__ bias2,
    const float* __restrict__ gamma,
    const float* __restrict__ beta,
    const float* __restrict__ bn_mean,
    const float* __restrict__ bn_var,
    const float* __restrict__ xres,
    int M, int K, int mode)
{
    const int b    = blockIdx.z;
    const int bx   = blockIdx.x;
    const int n0   = blockIdx.y * TBN;
    const int tid  = threadIdx.x;
    const int lane = tid & 31;
    const int wid  = tid >> 5;
    const int wm   = wid >> 2;
    const int wn   = wid & 3;

    const float* A;
    const float* bias;
    float* C;
    int m0;
    if (mode == 0) {
        A    = (bx == 0) ? A0 : (bx == 1) ? A1 : A2;
        bias = (bx == 0) ? bias0 : (bx == 1) ? bias1 : bias2;
        C    = (bx == 0) ? C0 : (bx == 1) ? C1 : C2;
        m0   = 0;
    } else {
        A = A0; bias = bias0; C = C0;
        m0 = bx * TBM;
    }

    const float* Bb = Bmat + (size_t)b * K * THW;
    float*       Cb = C    + (size_t)b * M * THW;

    __shared__ float As[2][TBM][APAD];
    __shared__ float Bs[2][TBK][BPAD];

    float acc[2][4][4];
#pragma unroll
    for (int i = 0; i < 2; i++)
#pragma unroll
        for (int j = 0; j < 4; j++)
#pragma unroll
            for (int q = 0; q < 4; q++) acc[i][j][q] = 0.f;

    const int row = lane >> 2;
    const int kc  = lane & 3;

    const int am = tid >> 2, ak = tid & 3;
    const int bk = tid >> 5, bn = tid & 31;

    uint32_t asBase = (uint32_t)__cvta_generic_to_shared(&As[0][0][0]);
    uint32_t bsBase = (uint32_t)__cvta_generic_to_shared(&Bs[0][0][0]);
    const uint32_t asStage = TBM * APAD * 4;
    const uint32_t bsStage = TBK * BPAD * 4;

    const int nkt = K / TBK;

    cpasync16(asBase + (am * APAD + ak * 4) * 4,
              A + (size_t)(m0 + am) * K + ak * 4);
    cpasync16(bsBase + (bk * BPAD + bn * 4) * 4,
              Bb + (size_t)bk * THW + n0 + bn * 4);
    asm volatile("cp.async.commit_group;\n");

    for (int i = 0; i < nkt; i++) {
        const int s = i & 1;
        if (i + 1 < nkt) {
            const int kt = (i + 1) * TBK;
            const uint32_t so = (s ^ 1);
            cpasync16(asBase + so * asStage + (am * APAD + ak * 4) * 4,
                      A + (size_t)(m0 + am) * K + kt + ak * 4);
            cpasync16(bsBase + so * bsStage + (bk * BPAD + bn * 4) * 4,
                      Bb + (size_t)(kt + bk) * THW + n0 + bn * 4);
            asm volatile("cp.async.commit_group;\n");
            asm volatile("cp.async.wait_group 1;\n");
        } else {
            asm volatile("cp.async.wait_group 0;\n");
        }
        __syncthreads();

#pragma unroll
        for (int ks = 0; ks < 2; ks++) {
            const int kb = ks * 8;
            uint32_t af[2][4];
#pragma unroll
            for (int mt = 0; mt < 2; mt++) {
                int mr = wm * 32 + mt * 16 + row;
                af[mt][0] = __float_as_uint(As[s][mr    ][kb + kc    ]);
                af[mt][1] = __float_as_uint(As[s][mr + 8][kb + kc    ]);
                af[mt][2] = __float_as_uint(As[s][mr    ][kb + kc + 4]);
                af[mt][3] = __float_as_uint(As[s][mr + 8][kb + kc + 4]);
            }
            uint32_t bf[4][2];
#pragma unroll
            for (int nt = 0; nt < 4; nt++) {
                int nc = wn * 32 + nt * 8 + row;
                if (CVTB) {
                    bf[nt][0] = f2tf32(Bs[s][kb + kc    ][nc]);
                    bf[nt][1] = f2tf32(Bs[s][kb + kc + 4][nc]);
                } else {
                    bf[nt][0] = __float_as_uint(Bs[s][kb + kc    ][nc]);
                    bf[nt][1] = __float_as_uint(Bs[s][kb + kc + 4][nc]);
                }
            }
#pragma unroll
            for (int mt = 0; mt < 2; mt++)
#pragma unroll
                for (int nt = 0; nt < 4; nt++) {
                    asm volatile(
                        "mma.sync.aligned.m16n8k8.row.col.f32.tf32.tf32.f32 "
                        "{%0,%1,%2,%3}, {%4,%5,%6,%7}, {%8,%9}, {%0,%1,%2,%3};"
                        : "+f"(acc[mt][nt][0]), "+f"(acc[mt][nt][1]),
                          "+f"(acc[mt][nt][2]), "+f"(acc[mt][nt][3])
                        : "r"(af[mt][0]), "r"(af[mt][1]),
                          "r"(af[mt][2]), "r"(af[mt][3]),
                          "r"(bf[nt][0]), "r"(bf[nt][1]));
                }
        }
        __syncthreads();
    }

    const int coln = 2 * (lane & 3);
#pragma unroll
    for (int mt = 0; mt < 2; mt++) {
#pragma unroll
        for (int half = 0; half < 2; half++) {
            int m = m0 + wm * 32 + mt * 16 + row + half * 8;
            float bi = bias[m];
            float sc = 1.f, sh = 0.f;
            if (mode == 1) {
                sc = gamma[m] * rsqrtf(bn_var[m] + BN_EPS);
                sh = beta[m] - bn_mean[m] * sc;
            }
#pragma unroll
            for (int nt = 0; nt < 4; nt++) {
                int n = n0 + wn * 32 + nt * 8 + coln;
                float v0 = acc[mt][nt][half * 2 + 0] + bi;
                float v1 = acc[mt][nt][half * 2 + 1] + bi;
                if (mode == 1) {
                    const float* xr = xres + (size_t)b * CC * THW + (size_t)m * THW + n;
                    v0 = v0 * sc + sh + xr[0];
                    v1 = v1 * sc + sh + xr[1];
                }
                *reinterpret_cast<float2*>(&Cb[(size_t)m * THW + n]) =
                    make_float2(v0, v1);
            }
        }
    }
}

// ---------------------------------------------------------------------------
// Pruned warp top-k (unchanged — known good)
// ---------------------------------------------------------------------------
template<int J>
__device__ __forceinline__ void shflStepRT(float* v, bool tm) {
#pragma unroll
    for (int r = 0; r < 32; r++) {
        float p  = __shfl_xor_sync(0xffffffffu, v[r], J);
        float mn = fminf(v[r], p), mx = fmaxf(v[r], p);
        v[r] = tm ? mx : mn;
    }
}
template<int J, int KR>
__device__ __forceinline__ void shflStepCT(float* v, bool loJ) {
#pragma unroll
    for (int r = 0; r < 32; r++) {
        const bool tm = ((r & KR) == 0) ? true : false;
        float p  = __shfl_xor_sync(0xffffffffu, v[r], J);
        float mn = fminf(v[r], p), mx = fmaxf(v[r], p);
        v[r] = (tm ? loJ : !loJ) ? mx : mn;
    }
}
template<int JR, int KR>
__device__ __forceinline__ void regStep(float* v) {
#pragma unroll
    for (int r = 0; r < 32; r++) if (!(r & JR)) {
        float a = v[r], b = v[r | JR];
        if ((r & KR) == 0) { v[r] = fmaxf(a, b); v[r | JR] = fminf(a, b); }
        else               { v[r] = fminf(a, b); v[r | JR] = fmaxf(a, b); }
    }
}
template<int KR>
__device__ __forceinline__ void shflSweepCT(float* v, bool lo16, bool lo8,
                                            bool lo4, bool lo2, bool lo1) {
    shflStepCT<16, KR>(v, lo16);
    shflStepCT<8,  KR>(v, lo8);
    shflStepCT<4,  KR>(v, lo4);
    shflStepCT<2,  KR>(v, lo2);
    shflStepCT<1,  KR>(v, lo1);
}
template<int JR>
__device__ __forceinline__ void mergeStepDual(float* v) {
#pragma unroll
    for (int q = 0; q < 8; q++) if (!(q & JR)) {
        { float a = v[q], b = v[q | JR];
          v[q] = fmaxf(a, b); v[q | JR] = fminf(a, b); }
        { float a = v[16 + q], b = v[16 + (q | JR)];
          v[16 + q] = fminf(a, b); v[16 + (q | JR)] = fmaxf(a, b); }
    }
}
template<int J>
__device__ __forceinline__ void shflMergeDual(float* v, bool loJ) {
#pragma unroll
    for (int q = 0; q < 8; q++) {
        { float p = __shfl_xor_sync(0xffffffffu, v[q], J);
          float mn = fminf(v[q], p), mx = fmaxf(v[q], p);
          v[q] = loJ ? mx : mn; }
        { float p = __shfl_xor_sync(0xffffffffu, v[16 + q], J);
          float mn = fminf(v[16 + q], p), mx = fmaxf(v[16 + q], p);
          v[16 + q] = loJ ? mn : mx; }
    }
}
template<int JR>
__device__ __forceinline__ void mergeStepFinal(float* v) {
#pragma unroll
    for (int q = 0; q < 8; q++) if (!(q & JR)) {
        float a = v[q], b = v[q | JR];
        v[q] = fmaxf(a, b); v[q | JR] = fminf(a, b);
    }
}
template<int J>
__device__ __forceinline__ void shflFinal(float* v, bool loJ) {
#pragma unroll
    for (int q = 0; q < 8; q++) {
        float p  = __shfl_xor_sync(0xffffffffu, v[q], J);
        float mn = fminf(v[q], p), mx = fmaxf(v[q], p);
        v[q] = loJ ? mx : mn;
    }
}

__global__ __launch_bounds__(256) void topk_warp_kernel(
    const float* __restrict__ srcQ, float* __restrict__ dstQ,
    const float* __restrict__ srcK, float* __restrict__ dstK, int nrows)
{
    const int lane = threadIdx.x & 31;
    const int row  = blockIdx.x * (blockDim.x >> 5) + (threadIdx.x >> 5);
    if (row >= nrows) return;

    const float* src = blockIdx.y ? srcK : srcQ;
    float*       dst = blockIdx.y ? dstK : dstQ;

    const float* rp = src + (size_t)row * HWD;
    float v[32];
#pragma unroll
    for (int r = 0; r < 24; r++) v[r] = rp[r * 32 + lane];
    v[24] = (lane < 16) ? rp[24 * 32 + lane] : -CUDART_INF_F;
#pragma unroll
    for (int r = 25; r < 32; r++) v[r] = -CUDART_INF_F;

    const bool lo1  = (lane & 1)  == 0;
    const bool lo2  = (lane & 2)  == 0;
    const bool lo4  = (lane & 4)  == 0;
    const bool lo8  = (lane & 8)  == 0;
    const bool lo16 = (lane & 16) == 0;

    shflStepRT<1>(v, lo2 == lo1);
    shflStepRT<2>(v, lo4 == lo2);
    shflStepRT<1>(v, lo4 == lo1);
    shflStepRT<4>(v, lo8 == lo4);
    shflStepRT<2>(v, lo8 == lo2);
    shflStepRT<1>(v, lo8 == lo1);
    shflStepRT<8>(v, lo16 == lo8);
    shflStepRT<4>(v, lo16 == lo4);
    shflStepRT<2>(v, lo16 == lo2);
    shflStepRT<1>(v, lo16 == lo1);

    shflSweepCT<1>(v, lo16, lo8, lo4, lo2, lo1);
    regStep<1, 2>(v);
    shflSweepCT<2>(v, lo16, lo8, lo4, lo2, lo1);
    regStep<2, 4>(v); regStep<1, 4>(v);
    shflSweepCT<4>(v, lo16, lo8, lo4, lo2, lo1);
    regStep<4, 8>(v); regStep<2, 8>(v); regStep<1, 8>(v);
    shflSweepCT<8>(v, lo16, lo8, lo4, lo2, lo1);

#pragma unroll
    for (int q = 0; q < 8; q++) {
        { float a = v[q],      b = v[q + 8];
          v[q]      = fmaxf(a, b); v[q + 8]  = fminf(a, b); }
        { float a = v[16 + q], b = v[24 + q];
          v[16 + q] = fmaxf(a, b); v[24 + q] = fminf(a, b); }
    }
    mergeStepDual<4>(v); mergeStepDual<2>(v); mergeStepDual<1>(v);
    shflMergeDual<16>(v, lo16); shflMergeDual<8>(v, lo8);
    shflMergeDual<4>(v, lo4);   shflMergeDual<2>(v, lo2);
    shflMergeDual<1>(v, lo1);
#pragma unroll
    for (int q = 0; q < 8; q++) v[q] = fmaxf(v[q], v[16 + q]);
    mergeStepFinal<4>(v); mergeStepFinal<2>(v); mergeStepFinal<1>(v);
    shflFinal<16>(v, lo16); shflFinal<8>(v, lo8);
    shflFinal<4>(v, lo4);   shflFinal<2>(v, lo2);
    shflFinal<1>(v, lo1);

    float* dp = dst + (size_t)row * KTOP;
#pragma unroll
    for (int r = 0; r < 6; r++) dp[r * 32 + lane] = v[r];
    if (lane < 4) dp[6 * 32 + lane] = v[6];
}

// ---------------------------------------------------------------------------
// Attention. One block per n. After softmax each warp w owns rows t=w, w+8:
// attention weights live in REGISTERS (no LDS in hot loop); V loads coalesced
// and L2-shared across warps. Y pre-rounded to tf32 (bit-identical downstream).
// ---------------------------------------------------------------------------
__global__ __launch_bounds__(256, 4) void attn_kernel(
    const float* __restrict__ Qt, const float* __restrict__ Kt,
    const float* __restrict__ V, float* __restrict__ Y)
{
    __shared__ float sQ[TT * KTOP];
    __shared__ float sK[TT * KTOP];
    __shared__ float sA[TT * TT];

    const int n    = blockIdx.x;
    const int tid  = threadIdx.x;
    const int lane = tid & 31;
    const int wid  = tid >> 5;          // 0..7

    const float* qb = Qt + (long)n * TT * KTOP;
    const float* kb = Kt + (long)n * TT * KTOP;
    for (int i = tid; i < TT * KTOP; i += 256) { sQ[i] = qb[i]; sK[i] = kb[i]; }
    __syncthreads();

    {
        int t = tid >> 4, s = tid & 15;
        const float4* q4 = reinterpret_cast<const float4*>(sQ + t * KTOP);
        const float4* k4 = reinterpret_cast<const float4*>(sK + s * KTOP);
        float acc = 0.f;
#pragma unroll 7
        for (int j = 0; j < KTOP / 4; j++) {
            float4 a = q4[j], b = k4[j];
            acc = fmaf(a.x, b.x, acc);
            acc = fmaf(a.y, b.y, acc);
            acc = fmaf(a.z, b.z, acc);
            acc = fmaf(a.w, b.w, acc);
        }
        sA[t * 16 + s] = acc;
    }
    __syncthreads();

    if (tid < TT) {
        int t = tid;
        float mx = -CUDART_INF_F;
#pragma unroll
        for (int s = 0; s < 16; s++) mx = fmaxf(mx, sA[t * 16 + s]);
        float sum = 0.f;
        float e[16];
#pragma unroll
        for (int s = 0; s < 16; s++) { e[s] = __expf(sA[t * 16 + s] - mx); sum += e[s]; }
        float inv = 1.f / sum;
#pragma unroll
        for (int s = 0; s < 16; s++) sA[t * 16 + s] = e[s] * inv;
    }
    __syncthreads();

    // Pull this warp's two attention rows into registers
    float a0r[TT], a1r[TT];
#pragma unroll
    for (int s = 0; s < TT; s++) {
        a0r[s] = sA[wid * 16 + s];
        a1r[s] = sA[(wid + 8) * 16 + s];
    }

    const float* vb = V + (long)n * THW;
    float* y0 = Y + (long)n * THW + (long)wid * HWD;
    float* y1 = Y + (long)n * THW + (long)(wid + 8) * HWD;

#pragma unroll 1
    for (int p = lane; p < HWD; p += 32) {
        float acc0 = 0.f, acc1 = 0.f;
#pragma unroll
        for (int s = 0; s < TT; s++) {
            float vv = vb[s * HWD + p];
            acc0 = fmaf(a0r[s], vv, acc0);
            acc1 = fmaf(a1r[s], vv, acc1);
        }
        y0[p] = __uint_as_float(f2tf32(acc0));
        y1[p] = __uint_as_float(f2tf32(acc1));
    }
}

// ---------------------------------------------------------------------------
extern "C" void kernel_launch(void* const* d_in, const int* in_sizes, int n_in,
                              void* d_out, int out_size)
{
    const float* x      = (const float*)d_in[0];
    const float* Wq     = (const float*)d_in[1];
    const float* bq     = (const float*)d_in[2];
    const float* Wk     = (const float*)d_in[3];
    const float* bk     = (const float*)d_in[4];
    const float* Wv     = (const float*)d_in[5];
    const float* bv     = (const float*)d_in[6];
    const float* Wr     = (const float*)d_in[7];
    const float* br     = (const float*)d_in[8];
    const float* gamma  = (const float*)d_in[9];
    const float* beta   = (const float*)d_in[10];
    const float* bnmean = (const float*)d_in[11];
    const float* bnvar  = (const float*)d_in[12];
    float* out = (float*)d_out;

    float *Qp, *Kp, *Vp, *Qtp, *Ktp, *Yp, *Wqt, *Wkt, *Wvt, *Wrt;
    cudaGetSymbolAddress((void**)&Qp,  g_Q);
    cudaGetSymbolAddress((void**)&Kp,  g_K);
    cudaGetSymbolAddress((void**)&Vp,  g_V);
    cudaGetSymbolAddress((void**)&Qtp, g_Qt);
    cudaGetSymbolAddress((void**)&Ktp, g_Kt);
    cudaGetSymbolAddress((void**)&Yp,  g_Y);
    cudaGetSymbolAddress((void**)&Wqt, g_Wqt);
    cudaGetSymbolAddress((void**)&Wkt, g_Wkt);
    cudaGetSymbolAddress((void**)&Wvt, g_Wvt);
    cudaGetSymbolAddress((void**)&Wrt, g_Wrt);

    dim3 gW(128, 4);
    wconv_kernel<<<gW, 256>>>(Wq, Wk, Wv, Wr, Wqt, Wkt, Wvt, Wrt);

    dim3 gQKV(3, THW / TBN, BB);             // (3, 98, 8)
    gemm_tf32_pipe_kernel<1><<<gQKV, 512>>>(
        Wqt, Wkt, Wvt, x, Qp, Kp, Vp, bq, bk, bv,
        nullptr, nullptr, nullptr, nullptr, nullptr, CR, CC, 0);

    const int nrows = NROW * TT;             // 16384
    const int wpb = 8;
    dim3 gTK((nrows + wpb - 1) / wpb, 2);
    topk_warp_kernel<<<gTK, 32 * wpb>>>(Qp, Qtp, Kp, Ktp, nrows);

    attn_kernel<<<NROW, 256>>>(Qtp, Ktp, Vp, Yp);

    dim3 gRec(CC / TBM, THW / TBN, BB);      // (2, 98, 8)
    gemm_tf32_pipe_kernel<0><<<gRec, 512>>>(
        Wrt, nullptr, nullptr, Yp, out, nullptr, nullptr, br, nullptr, nullptr,
        gamma, beta, bnmean, bnvar, x, CC, CR, 1);
}

// round 13
// speedup vs baseline: 1.2529x; 1.0212x over previous
#include <cuda_runtime.h>
#include <math_constants.h>
#include <cstdint>

// Problem constants
#define BB   8
#define CC   256
#define CR   128
#define TT   16
#define HWD  784            // 28*28
#define THW  12544          // 16*784
#define KTOP 196            // 784/4
#define NROW 1024           // B*CR
#define BN_EPS 1e-5f

// Scratch buffers
__device__ float g_Q [BB * CR * THW];
__device__ float g_K [BB * CR * THW];
__device__ float g_V [BB * CR * THW];
__device__ float g_Qt[NROW * TT * KTOP];
__device__ float g_Kt[NROW * TT * KTOP];
__device__ float g_Y [BB * CR * THW];
// Pre-converted (tf32-bit) weights
__device__ float g_Wqt[CR * CC];
__device__ float g_Wkt[CR * CC];
__device__ float g_Wvt[CR * CC];
__device__ float g_Wrt[CC * CR];

__device__ __forceinline__ uint32_t f2tf32(float x) {
    uint32_t u;
    asm("cvt.rna.tf32.f32 %0, %1;" : "=r"(u) : "f"(x));
    return u;
}
__device__ __forceinline__ void cpasync16(uint32_t daddr, const void* src) {
    asm volatile("cp.async.ca.shared.global [%0], [%1], 16;\n"
                 :: "r"(daddr), "l"(src));
}

// ---------------------------------------------------------------------------
// Weight tf32 preconversion
// ---------------------------------------------------------------------------
__global__ __launch_bounds__(256) void wconv_kernel(
    const float* __restrict__ w0, const float* __restrict__ w1,
    const float* __restrict__ w2, const float* __restrict__ w3,
    float* __restrict__ d0, float* __restrict__ d1,
    float* __restrict__ d2, float* __restrict__ d3)
{
    const int a = blockIdx.y;
    const float* s = (a == 0) ? w0 : (a == 1) ? w1 : (a == 2) ? w2 : w3;
    float*       d = (a == 0) ? d0 : (a == 1) ? d1 : (a == 2) ? d2 : d3;
    int i = blockIdx.x * 256 + threadIdx.x;
    d[i] = __uint_as_float(f2tf32(s[i]));
}

// ---------------------------------------------------------------------------
// Pipelined tf32 GEMM, 2-stage cp.async, 512 threads (16 warps, 4Mx4N).
// ---------------------------------------------------------------------------
#define TBM 128
#define TBN 128
#define TBK 16
#define APAD 20
#define BPAD 136

template<int CVTB>
__global__ __launch_bounds__(512) void gemm_tf32_pipe_kernel(
    const float* __restrict__ A0, const float* __restrict__ A1,
    const float* __restrict__ A2,
    const float* __restrict__ Bmat,
    float* __restrict__ C0, float* __restrict__ C1, float* __restrict__ C2,
    const float* __restrict__ bias0, const float* __restrict__ bias1,
    const float* __restrict__ bias2,
    const float* __restrict__ gamma,
    const float* __restrict__ beta,
    const float* __restrict__ bn_mean,
    const float* __restrict__ bn_var,
    const float* __restrict__ xres,
    int M, int K, int mode)
{
    const int b    = blockIdx.z;
    const int bx   = blockIdx.x;
    const int n0   = blockIdx.y * TBN;
    const int tid  = threadIdx.x;
    const int lane = tid & 31;
    const int wid  = tid >> 5;
    const int wm   = wid >> 2;
    const int wn   = wid & 3;

    const float* A;
    const float* bias;
    float* C;
    int m0;
    if (mode == 0) {
        A    = (bx == 0) ? A0 : (bx == 1) ? A1 : A2;
        bias = (bx == 0) ? bias0 : (bx == 1) ? bias1 : bias2;
        C    = (bx == 0) ? C0 : (bx == 1) ? C1 : C2;
        m0   = 0;
    } else {
        A = A0; bias = bias0; C = C0;
        m0 = bx * TBM;
    }

    const float* Bb = Bmat + (size_t)b * K * THW;
    float*       Cb = C    + (size_t)b * M * THW;

    __shared__ float As[2][TBM][APAD];
    __shared__ float Bs[2][TBK][BPAD];

    float acc[2][4][4];
#pragma unroll
    for (int i = 0; i < 2; i++)
#pragma unroll
        for (int j = 0; j < 4; j++)
#pragma unroll
            for (int q = 0; q < 4; q++) acc[i][j][q] = 0.f;

    const int row = lane >> 2;
    const int kc  = lane & 3;

    const int am = tid >> 2, ak = tid & 3;
    const int bk = tid >> 5, bn = tid & 31;

    uint32_t asBase = (uint32_t)__cvta_generic_to_shared(&As[0][0][0]);
    uint32_t bsBase = (uint32_t)__cvta_generic_to_shared(&Bs[0][0][0]);
    const uint32_t asStage = TBM * APAD * 4;
    const uint32_t bsStage = TBK * BPAD * 4;

    const int nkt = K / TBK;

    cpasync16(asBase + (am * APAD + ak * 4) * 4,
              A + (size_t)(m0 + am) * K + ak * 4);
    cpasync16(bsBase + (bk * BPAD + bn * 4) * 4,
              Bb + (size_t)bk * THW + n0 + bn * 4);
    asm volatile("cp.async.commit_group;\n");

    for (int i = 0; i < nkt; i++) {
        const int s = i & 1;
        if (i + 1 < nkt) {
            const int kt = (i + 1) * TBK;
            const uint32_t so = (s ^ 1);
            cpasync16(asBase + so * asStage + (am * APAD + ak * 4) * 4,
                      A + (size_t)(m0 + am) * K + kt + ak * 4);
            cpasync16(bsBase + so * bsStage + (bk * BPAD + bn * 4) * 4,
                      Bb + (size_t)(kt + bk) * THW + n0 + bn * 4);
            asm volatile("cp.async.commit_group;\n");
            asm volatile("cp.async.wait_group 1;\n");
        } else {
            asm volatile("cp.async.wait_group 0;\n");
        }
        __syncthreads();

#pragma unroll
        for (int ks = 0; ks < 2; ks++) {
            const int kb = ks * 8;
            uint32_t af[2][4];
#pragma unroll
            for (int mt = 0; mt < 2; mt++) {
                int mr = wm * 32 + mt * 16 + row;
                af[mt][0] = __float_as_uint(As[s][mr    ][kb + kc    ]);
                af[mt][1] = __float_as_uint(As[s][mr + 8][kb + kc    ]);
                af[mt][2] = __float_as_uint(As[s][mr    ][kb + kc + 4]);
                af[mt][3] = __float_as_uint(As[s][mr + 8][kb + kc + 4]);
            }
            uint32_t bf[4][2];
#pragma unroll
            for (int nt = 0; nt < 4; nt++) {
                int nc = wn * 32 + nt * 8 + row;
                if (CVTB) {
                    bf[nt][0] = f2tf32(Bs[s][kb + kc    ][nc]);
                    bf[nt][1] = f2tf32(Bs[s][kb + kc + 4][nc]);
                } else {
                    bf[nt][0] = __float_as_uint(Bs[s][kb + kc    ][nc]);
                    bf[nt][1] = __float_as_uint(Bs[s][kb + kc + 4][nc]);
                }
            }
#pragma unroll
            for (int mt = 0; mt < 2; mt++)
#pragma unroll
                for (int nt = 0; nt < 4; nt++) {
                    asm volatile(
                        "mma.sync.aligned.m16n8k8.row.col.f32.tf32.tf32.f32 "
                        "{%0,%1,%2,%3}, {%4,%5,%6,%7}, {%8,%9}, {%0,%1,%2,%3};"
                        : "+f"(acc[mt][nt][0]), "+f"(acc[mt][nt][1]),
                          "+f"(acc[mt][nt][2]), "+f"(acc[mt][nt][3])
                        : "r"(af[mt][0]), "r"(af[mt][1]),
                          "r"(af[mt][2]), "r"(af[mt][3]),
                          "r"(bf[nt][0]), "r"(bf[nt][1]));
                }
        }
        __syncthreads();
    }

    const int coln = 2 * (lane & 3);
#pragma unroll
    for (int mt = 0; mt < 2; mt++) {
#pragma unroll
        for (int half = 0; half < 2; half++) {
            int m = m0 + wm * 32 + mt * 16 + row + half * 8;
            float bi = bias[m];
            float sc = 1.f, sh = 0.f;
            if (mode == 1) {
                sc = gamma[m] * rsqrtf(bn_var[m] + BN_EPS);
                sh = beta[m] - bn_mean[m] * sc;
            }
#pragma unroll
            for (int nt = 0; nt < 4; nt++) {
                int n = n0 + wn * 32 + nt * 8 + coln;
                float v0 = acc[mt][nt][half * 2 + 0] + bi;
                float v1 = acc[mt][nt][half * 2 + 1] + bi;
                if (mode == 1) {
                    const float* xr = xres + (size_t)b * CC * THW + (size_t)m * THW + n;
                    v0 = v0 * sc + sh + xr[0];
                    v1 = v1 * sc + sh + xr[1];
                }
                *reinterpret_cast<float2*>(&Cb[(size_t)m * THW + n]) =
                    make_float2(v0, v1);
            }
        }
    }
}

// ---------------------------------------------------------------------------
// Pruned warp top-k. Layout idx = r*32 + lane.
// Chunk 3 (r24..31) holds only 16 real values: pre-sorted with a single
// 32-lane bitonic into r31 lanes16..31 (ascending chunk layout); all sort
// stages run only on r<24 (RMAX). Selection tail unchanged.
// ---------------------------------------------------------------------------
template<int J, int RMAX>
__device__ __forceinline__ void shflStepRT(float* v, bool tm) {
#pragma unroll
    for (int r = 0; r < RMAX; r++) {
        float p  = __shfl_xor_sync(0xffffffffu, v[r], J);
        float mn = fminf(v[r], p), mx = fmaxf(v[r], p);
        v[r] = tm ? mx : mn;
    }
}
template<int J, int KR, int RMAX>
__device__ __forceinline__ void shflStepCT(float* v, bool loJ) {
#pragma unroll
    for (int r = 0; r < RMAX; r++) {
        const bool tm = ((r & KR) == 0) ? true : false;
        float p  = __shfl_xor_sync(0xffffffffu, v[r], J);
        float mn = fminf(v[r], p), mx = fmaxf(v[r], p);
        v[r] = (tm ? loJ : !loJ) ? mx : mn;
    }
}
template<int JR, int KR, int RMAX>
__device__ __forceinline__ void regStep(float* v) {
#pragma unroll
    for (int r = 0; r < RMAX; r++) if (!(r & JR)) {
        float a = v[r], b = v[r | JR];
        if ((r & KR) == 0) { v[r] = fmaxf(a, b); v[r | JR] = fminf(a, b); }
        else               { v[r] = fminf(a, b); v[r | JR] = fmaxf(a, b); }
    }
}
template<int KR, int RMAX>
__device__ __forceinline__ void shflSweepCT(float* v, bool lo16, bool lo8,
                                            bool lo4, bool lo2, bool lo1) {
    shflStepCT<16, KR, RMAX>(v, lo16);
    shflStepCT<8,  KR, RMAX>(v, lo8);
    shflStepCT<4,  KR, RMAX>(v, lo4);
    shflStepCT<2,  KR, RMAX>(v, lo2);
    shflStepCT<1,  KR, RMAX>(v, lo1);
}
template<int JR>
__device__ __forceinline__ void mergeStepDual(float* v) {
#pragma unroll
    for (int q = 0; q < 8; q++) if (!(q & JR)) {
        { float a = v[q], b = v[q | JR];
          v[q] = fmaxf(a, b); v[q | JR] = fminf(a, b); }
        { float a = v[16 + q], b = v[16 + (q | JR)];
          v[16 + q] = fminf(a, b); v[16 + (q | JR)] = fmaxf(a, b); }
    }
}
template<int J>
__device__ __forceinline__ void shflMergeDual(float* v, bool loJ) {
#pragma unroll
    for (int q = 0; q < 8; q++) {
        { float p = __shfl_xor_sync(0xffffffffu, v[q], J);
          float mn = fminf(v[q], p), mx = fmaxf(v[q], p);
          v[q] = loJ ? mx : mn; }
        { float p = __shfl_xor_sync(0xffffffffu, v[16 + q], J);
          float mn = fminf(v[16 + q], p), mx = fmaxf(v[16 + q], p);
          v[16 + q] = loJ ? mn : mx; }
    }
}
template<int JR>
__device__ __forceinline__ void mergeStepFinal(float* v) {
#pragma unroll
    for (int q = 0; q < 8; q++) if (!(q & JR)) {
        float a = v[q], b = v[q | JR];
        v[q] = fmaxf(a, b); v[q | JR] = fminf(a, b);
    }
}
template<int J>
__device__ __forceinline__ void shflFinal(float* v, bool loJ) {
#pragma unroll
    for (int q = 0; q < 8; q++) {
        float p  = __shfl_xor_sync(0xffffffffu, v[q], J);
        float mn = fminf(v[q], p), mx = fmaxf(v[q], p);
        v[q] = loJ ? mx : mn;
    }
}

__global__ __launch_bounds__(256) void topk_warp_kernel(
    const float* __restrict__ srcQ, float* __restrict__ dstQ,
    const float* __restrict__ srcK, float* __restrict__ dstK, int nrows)
{
    const int lane = threadIdx.x & 31;
    const int row  = blockIdx.x * (blockDim.x >> 5) + (threadIdx.x >> 5);
    if (row >= nrows) return;

    const float* src = blockIdx.y ? srcK : srcQ;
    float*       dst = blockIdx.y ? dstK : dstQ;

    const float* rp = src + (size_t)row * HWD;
    float v[32];
#pragma unroll
    for (int r = 0; r < 24; r++) v[r] = rp[r * 32 + lane];
#pragma unroll
    for (int r = 24; r < 32; r++) v[r] = -CUDART_INF_F;

    // --- chunk 3: sort the 16 tail reals (idx 768..783) ascending across the
    // warp (pad with -inf): result lands reals-ascending at lanes 16..31.
    {
        float t = (lane < 16) ? rp[24 * 32 + lane] : -CUDART_INF_F;
#pragma unroll
        for (int k = 2; k <= 32; k <<= 1) {
#pragma unroll
            for (int j = 16; j > 0; j >>= 1) {
                if (j < k) {
                    bool up = ((lane & k) == 0) || (k == 32);
                    float p = __shfl_xor_sync(0xffffffffu, t, j);
                    bool take_min = (((lane & j) == 0) == up);
                    float mn = fminf(t, p), mx = fmaxf(t, p);
                    t = take_min ? mn : mx;
                }
            }
        }
        v[31] = t;   // idx 992..1023 ascending: -infs then 16 reals
    }

    const bool lo1  = (lane & 1)  == 0;
    const bool lo2  = (lane & 2)  == 0;
    const bool lo4  = (lane & 4)  == 0;
    const bool lo8  = (lane & 8)  == 0;
    const bool lo16 = (lane & 16) == 0;

    // ---- sort chunks 0..2 only (r<24) ----
    shflStepRT<1, 24>(v, lo2 == lo1);
    shflStepRT<2, 24>(v, lo4 == lo2);
    shflStepRT<1, 24>(v, lo4 == lo1);
    shflStepRT<4, 24>(v, lo8 == lo4);
    shflStepRT<2, 24>(v, lo8 == lo2);
    shflStepRT<1, 24>(v, lo8 == lo1);
    shflStepRT<8, 24>(v, lo16 == lo8);
    shflStepRT<4, 24>(v, lo16 == lo4);
    shflStepRT<2, 24>(v, lo16 == lo2);
    shflStepRT<1, 24>(v, lo16 == lo1);

    shflSweepCT<1, 24>(v, lo16, lo8, lo4, lo2, lo1);             // k=32
    regStep<1, 2, 24>(v);
    shflSweepCT<2, 24>(v, lo16, lo8, lo4, lo2, lo1);             // k=64
    regStep<2, 4, 24>(v); regStep<1, 4, 24>(v);
    shflSweepCT<4, 24>(v, lo16, lo8, lo4, lo2, lo1);             // k=128
    regStep<4, 8, 24>(v); regStep<2, 8, 24>(v); regStep<1, 8, 24>(v);
    shflSweepCT<8, 24>(v, lo16, lo8, lo4, lo2, lo1);             // k=256

    // ---- selection tail (unchanged) ----
#pragma unroll
    for (int q = 0; q < 8; q++) {
        { float a = v[q],      b = v[q + 8];
          v[q]      = fmaxf(a, b); v[q + 8]  = fminf(a, b); }
        { float a = v[16 + q], b = v[24 + q];
          v[16 + q] = fmaxf(a, b); v[24 + q] = fminf(a, b); }
    }
    mergeStepDual<4>(v); mergeStepDual<2>(v); mergeStepDual<1>(v);
    shflMergeDual<16>(v, lo16); shflMergeDual<8>(v, lo8);
    shflMergeDual<4>(v, lo4);   shflMergeDual<2>(v, lo2);
    shflMergeDual<1>(v, lo1);
#pragma unroll
    for (int q = 0; q < 8; q++) v[q] = fmaxf(v[q], v[16 + q]);
    mergeStepFinal<4>(v); mergeStepFinal<2>(v); mergeStepFinal<1>(v);
    shflFinal<16>(v, lo16); shflFinal<8>(v, lo8);
    shflFinal<4>(v, lo4);   shflFinal<2>(v, lo2);
    shflFinal<1>(v, lo1);

    float* dp = dst + (size_t)row * KTOP;
#pragma unroll
    for (int r = 0; r < 6; r++) dp[r * 32 + lane] = v[r];
    if (lane < 4) dp[6 * 32 + lane] = v[6];
}

// ---------------------------------------------------------------------------
// Attention (unchanged from R12 — known good)
// ---------------------------------------------------------------------------
__global__ __launch_bounds__(256, 4) void attn_kernel(
    const float* __restrict__ Qt, const float* __restrict__ Kt,
    const float* __restrict__ V, float* __restrict__ Y)
{
    __shared__ float sQ[TT * KTOP];
    __shared__ float sK[TT * KTOP];
    __shared__ float sA[TT * TT];

    const int n    = blockIdx.x;
    const int tid  = threadIdx.x;
    const int lane = tid & 31;
    const int wid  = tid >> 5;

    const float* qb = Qt + (long)n * TT * KTOP;
    const float* kb = Kt + (long)n * TT * KTOP;
    for (int i = tid; i < TT * KTOP; i += 256) { sQ[i] = qb[i]; sK[i] = kb[i]; }
    __syncthreads();

    {
        int t = tid >> 4, s = tid & 15;
        const float4* q4 = reinterpret_cast<const float4*>(sQ + t * KTOP);
        const float4* k4 = reinterpret_cast<const float4*>(sK + s * KTOP);
        float acc = 0.f;
#pragma unroll 7
        for (int j = 0; j < KTOP / 4; j++) {
            float4 a = q4[j], b = k4[j];
            acc = fmaf(a.x, b.x, acc);
            acc = fmaf(a.y, b.y, acc);
            acc = fmaf(a.z, b.z, acc);
            acc = fmaf(a.w, b.w, acc);
        }
        sA[t * 16 + s] = acc;
    }
    __syncthreads();

    if (tid < TT) {
        int t = tid;
        float mx = -CUDART_INF_F;
#pragma unroll
        for (int s = 0; s < 16; s++) mx = fmaxf(mx, sA[t * 16 + s]);
        float sum = 0.f;
        float e[16];
#pragma unroll
        for (int s = 0; s < 16; s++) { e[s] = __expf(sA[t * 16 + s] - mx); sum += e[s]; }
        float inv = 1.f / sum;
#pragma unroll
        for (int s = 0; s < 16; s++) sA[t * 16 + s] = e[s] * inv;
    }
    __syncthreads();

    float a0r[TT], a1r[TT];
#pragma unroll
    for (int s = 0; s < TT; s++) {
        a0r[s] = sA[wid * 16 + s];
        a1r[s] = sA[(wid + 8) * 16 + s];
    }

    const float* vb = V + (long)n * THW;
    float* y0 = Y + (long)n * THW + (long)wid * HWD;
    float* y1 = Y + (long)n * THW + (long)(wid + 8) * HWD;

#pragma unroll 1
    for (int p = lane; p < HWD; p += 32) {
        float acc0 = 0.f, acc1 = 0.f;
#pragma unroll
        for (int s = 0; s < TT; s++) {
            float vv = vb[s * HWD + p];
            acc0 = fmaf(a0r[s], vv, acc0);
            acc1 = fmaf(a1r[s], vv, acc1);
        }
        y0[p] = __uint_as_float(f2tf32(acc0));
        y1[p] = __uint_as_float(f2tf32(acc1));
    }
}

// ---------------------------------------------------------------------------
extern "C" void kernel_launch(void* const* d_in, const int* in_sizes, int n_in,
                              void* d_out, int out_size)
{
    const float* x      = (const float*)d_in[0];
    const float* Wq     = (const float*)d_in[1];
    const float* bq     = (const float*)d_in[2];
    const float* Wk     = (const float*)d_in[3];
    const float* bk     = (const float*)d_in[4];
    const float* Wv     = (const float*)d_in[5];
    const float* bv     = (const float*)d_in[6];
    const float* Wr     = (const float*)d_in[7];
    const float* br     = (const float*)d_in[8];
    const float* gamma  = (const float*)d_in[9];
    const float* beta   = (const float*)d_in[10];
    const float* bnmean = (const float*)d_in[11];
    const float* bnvar  = (const float*)d_in[12];
    float* out = (float*)d_out;

    float *Qp, *Kp, *Vp, *Qtp, *Ktp, *Yp, *Wqt, *Wkt, *Wvt, *Wrt;
    cudaGetSymbolAddress((void**)&Qp,  g_Q);
    cudaGetSymbolAddress((void**)&Kp,  g_K);
    cudaGetSymbolAddress((void**)&Vp,  g_V);
    cudaGetSymbolAddress((void**)&Qtp, g_Qt);
    cudaGetSymbolAddress((void**)&Ktp, g_Kt);
    cudaGetSymbolAddress((void**)&Yp,  g_Y);
    cudaGetSymbolAddress((void**)&Wqt, g_Wqt);
    cudaGetSymbolAddress((void**)&Wkt, g_Wkt);
    cudaGetSymbolAddress((void**)&Wvt, g_Wvt);
    cudaGetSymbolAddress((void**)&Wrt, g_Wrt);

    dim3 gW(128, 4);
    wconv_kernel<<<gW, 256>>>(Wq, Wk, Wv, Wr, Wqt, Wkt, Wvt, Wrt);

    dim3 gQKV(3, THW / TBN, BB);             // (3, 98, 8)
    gemm_tf32_pipe_kernel<1><<<gQKV, 512>>>(
        Wqt, Wkt, Wvt, x, Qp, Kp, Vp, bq, bk, bv,
        nullptr, nullptr, nullptr, nullptr, nullptr, CR, CC, 0);

    const int nrows = NROW * TT;             // 16384
    const int wpb = 8;
    dim3 gTK((nrows + wpb - 1) / wpb, 2);
    topk_warp_kernel<<<gTK, 32 * wpb>>>(Qp, Qtp, Kp, Ktp, nrows);

    attn_kernel<<<NROW, 256>>>(Qtp, Ktp, Vp, Yp);

    dim3 gRec(CC / TBM, THW / TBN, BB);      // (2, 98, 8)
    gemm_tf32_pipe_kernel<0><<<gRec, 512>>>(
        Wrt, nullptr, nullptr, Yp, out, nullptr, nullptr, br, nullptr, nullptr,
        gamma, beta, bnmean, bnvar, x, CC, CR, 1);
}

// round 14
// speedup vs baseline: 1.2664x; 1.0108x over previous
#include <cuda_runtime.h>
#include <math_constants.h>
#include <cstdint>

// Problem constants
#define BB   8
#define CC   256
#define CR   128
#define TT   16
#define HWD  784            // 28*28
#define THW  12544          // 16*784
#define KTOP 196            // 784/4
#define NROW 1024           // B*CR
#define BN_EPS 1e-5f

// Scratch buffers
__device__ float g_Q [BB * CR * THW];
__device__ float g_K [BB * CR * THW];
__device__ float g_V [BB * CR * THW];
__device__ float g_Qt[NROW * TT * KTOP];
__device__ float g_Kt[NROW * TT * KTOP];
__device__ float g_Y [BB * CR * THW];
// Pre-converted (tf32-bit) weights
__device__ float g_Wqt[CR * CC];
__device__ float g_Wkt[CR * CC];
__device__ float g_Wvt[CR * CC];
__device__ float g_Wrt[CC * CR];

__device__ __forceinline__ uint32_t f2tf32(float x) {
    uint32_t u;
    asm("cvt.rna.tf32.f32 %0, %1;" : "=r"(u) : "f"(x));
    return u;
}
__device__ __forceinline__ float f2tf32f(float x) {
    return __uint_as_float(f2tf32(x));
}
__device__ __forceinline__ void cpasync16(uint32_t daddr, const void* src) {
    asm volatile("cp.async.ca.shared.global [%0], [%1], 16;\n"
                 :: "r"(daddr), "l"(src));
}

// ---------------------------------------------------------------------------
// Weight tf32 preconversion
// ---------------------------------------------------------------------------
__global__ __launch_bounds__(256) void wconv_kernel(
    const float* __restrict__ w0, const float* __restrict__ w1,
    const float* __restrict__ w2, const float* __restrict__ w3,
    float* __restrict__ d0, float* __restrict__ d1,
    float* __restrict__ d2, float* __restrict__ d3)
{
    const int a = blockIdx.y;
    const float* s = (a == 0) ? w0 : (a == 1) ? w1 : (a == 2) ? w2 : w3;
    float*       d = (a == 0) ? d0 : (a == 1) ? d1 : (a == 2) ? d2 : d3;
    int i = blockIdx.x * 256 + threadIdx.x;
    d[i] = __uint_as_float(f2tf32(s[i]));
}

// ---------------------------------------------------------------------------
// Pipelined tf32 GEMM, 2-stage cp.async, 512 threads (16 warps, 4Mx4N).
// ---------------------------------------------------------------------------
#define TBM 128
#define TBN 128
#define TBK 16
#define APAD 20
#define BPAD 136

template<int CVTB>
__global__ __launch_bounds__(512) void gemm_tf32_pipe_kernel(
    const float* __restrict__ A0, const float* __restrict__ A1,
    const float* __restrict__ A2,
    const float* __restrict__ Bmat,
    float* __restrict__ C0, float* __restrict__ C1, float* __restrict__ C2,
    const float* __restrict__ bias0, const float* __restrict__ bias1,
    const float* __restrict__ bias2,
    const float* __restrict__ gamma,
    const float* __restrict__ beta,
    const float* __restrict__ bn_mean,
    const float* __restrict__ bn_var,
    const float* __restrict__ xres,
    int M, int K, int mode)
{
    const int b    = blockIdx.z;
    const int bx   = blockIdx.x;
    const int n0   = blockIdx.y * TBN;
    const int tid  = threadIdx.x;
    const int lane = tid & 31;
    const int wid  = tid >> 5;
    const int wm   = wid >> 2;
    const int wn   = wid & 3;

    const float* A;
    const float* bias;
    float* C;
    int m0;
    if (mode == 0) {
        A    = (bx == 0) ? A0 : (bx == 1) ? A1 : A2;
        bias = (bx == 0) ? bias0 : (bx == 1) ? bias1 : bias2;
        C    = (bx == 0) ? C0 : (bx == 1) ? C1 : C2;
        m0   = 0;
    } else {
        A = A0; bias = bias0; C = C0;
        m0 = bx * TBM;
    }

    const float* Bb = Bmat + (size_t)b * K * THW;
    float*       Cb = C    + (size_t)b * M * THW;

    __shared__ float As[2][TBM][APAD];
    __shared__ float Bs[2][TBK][BPAD];

    float acc[2][4][4];
#pragma unroll
    for (int i = 0; i < 2; i++)
#pragma unroll
        for (int j = 0; j < 4; j++)
#pragma unroll
            for (int q = 0; q < 4; q++) acc[i][j][q] = 0.f;

    const int row = lane >> 2;
    const int kc  = lane & 3;

    const int am = tid >> 2, ak = tid & 3;
    const int bk = tid >> 5, bn = tid & 31;

    uint32_t asBase = (uint32_t)__cvta_generic_to_shared(&As[0][0][0]);
    uint32_t bsBase = (uint32_t)__cvta_generic_to_shared(&Bs[0][0][0]);
    const uint32_t asStage = TBM * APAD * 4;
    const uint32_t bsStage = TBK * BPAD * 4;

    const int nkt = K / TBK;

    cpasync16(asBase + (am * APAD + ak * 4) * 4,
              A + (size_t)(m0 + am) * K + ak * 4);
    cpasync16(bsBase + (bk * BPAD + bn * 4) * 4,
              Bb + (size_t)bk * THW + n0 + bn * 4);
    asm volatile("cp.async.commit_group;\n");

    for (int i = 0; i < nkt; i++) {
        const int s = i & 1;
        if (i + 1 < nkt) {
            const int kt = (i + 1) * TBK;
            const uint32_t so = (s ^ 1);
            cpasync16(asBase + so * asStage + (am * APAD + ak * 4) * 4,
                      A + (size_t)(m0 + am) * K + kt + ak * 4);
            cpasync16(bsBase + so * bsStage + (bk * BPAD + bn * 4) * 4,
                      Bb + (size_t)(kt + bk) * THW + n0 + bn * 4);
            asm volatile("cp.async.commit_group;\n");
            asm volatile("cp.async.wait_group 1;\n");
        } else {
            asm volatile("cp.async.wait_group 0;\n");
        }
        __syncthreads();

#pragma unroll
        for (int ks = 0; ks < 2; ks++) {
            const int kb = ks * 8;
            uint32_t af[2][4];
#pragma unroll
            for (int mt = 0; mt < 2; mt++) {
                int mr = wm * 32 + mt * 16 + row;
                af[mt][0] = __float_as_uint(As[s][mr    ][kb + kc    ]);
                af[mt][1] = __float_as_uint(As[s][mr + 8][kb + kc    ]);
                af[mt][2] = __float_as_uint(As[s][mr    ][kb + kc + 4]);
                af[mt][3] = __float_as_uint(As[s][mr + 8][kb + kc + 4]);
            }
            uint32_t bf[4][2];
#pragma unroll
            for (int nt = 0; nt < 4; nt++) {
                int nc = wn * 32 + nt * 8 + row;
                if (CVTB) {
                    bf[nt][0] = f2tf32(Bs[s][kb + kc    ][nc]);
                    bf[nt][1] = f2tf32(Bs[s][kb + kc + 4][nc]);
                } else {
                    bf[nt][0] = __float_as_uint(Bs[s][kb + kc    ][nc]);
                    bf[nt][1] = __float_as_uint(Bs[s][kb + kc + 4][nc]);
                }
            }
#pragma unroll
            for (int mt = 0; mt < 2; mt++)
#pragma unroll
                for (int nt = 0; nt < 4; nt++) {
                    asm volatile(
                        "mma.sync.aligned.m16n8k8.row.col.f32.tf32.tf32.f32 "
                        "{%0,%1,%2,%3}, {%4,%5,%6,%7}, {%8,%9}, {%0,%1,%2,%3};"
                        : "+f"(acc[mt][nt][0]), "+f"(acc[mt][nt][1]),
                          "+f"(acc[mt][nt][2]), "+f"(acc[mt][nt][3])
                        : "r"(af[mt][0]), "r"(af[mt][1]),
                          "r"(af[mt][2]), "r"(af[mt][3]),
                          "r"(bf[nt][0]), "r"(bf[nt][1]));
                }
        }
        __syncthreads();
    }

    const int coln = 2 * (lane & 3);
#pragma unroll
    for (int mt = 0; mt < 2; mt++) {
#pragma unroll
        for (int half = 0; half < 2; half++) {
            int m = m0 + wm * 32 + mt * 16 + row + half * 8;
            float bi = bias[m];
            float sc = 1.f, sh = 0.f;
            if (mode == 1) {
                sc = gamma[m] * rsqrtf(bn_var[m] + BN_EPS);
                sh = beta[m] - bn_mean[m] * sc;
            }
#pragma unroll
            for (int nt = 0; nt < 4; nt++) {
                int n = n0 + wn * 32 + nt * 8 + coln;
                float v0 = acc[mt][nt][half * 2 + 0] + bi;
                float v1 = acc[mt][nt][half * 2 + 1] + bi;
                if (mode == 1) {
                    const float* xr = xres + (size_t)b * CC * THW + (size_t)m * THW + n;
                    v0 = v0 * sc + sh + xr[0];
                    v1 = v1 * sc + sh + xr[1];
                }
                *reinterpret_cast<float2*>(&Cb[(size_t)m * THW + n]) =
                    make_float2(v0, v1);
            }
        }
    }
}

// ---------------------------------------------------------------------------
// Pruned warp top-k (unchanged from R13 — known good)
// ---------------------------------------------------------------------------
template<int J, int RMAX>
__device__ __forceinline__ void shflStepRT(float* v, bool tm) {
#pragma unroll
    for (int r = 0; r < RMAX; r++) {
        float p  = __shfl_xor_sync(0xffffffffu, v[r], J);
        float mn = fminf(v[r], p), mx = fmaxf(v[r], p);
        v[r] = tm ? mx : mn;
    }
}
template<int J, int KR, int RMAX>
__device__ __forceinline__ void shflStepCT(float* v, bool loJ) {
#pragma unroll
    for (int r = 0; r < RMAX; r++) {
        const bool tm = ((r & KR) == 0) ? true : false;
        float p  = __shfl_xor_sync(0xffffffffu, v[r], J);
        float mn = fminf(v[r], p), mx = fmaxf(v[r], p);
        v[r] = (tm ? loJ : !loJ) ? mx : mn;
    }
}
template<int JR, int KR, int RMAX>
__device__ __forceinline__ void regStep(float* v) {
#pragma unroll
    for (int r = 0; r < RMAX; r++) if (!(r & JR)) {
        float a = v[r], b = v[r | JR];
        if ((r & KR) == 0) { v[r] = fmaxf(a, b); v[r | JR] = fminf(a, b); }
        else               { v[r] = fminf(a, b); v[r | JR] = fmaxf(a, b); }
    }
}
template<int KR, int RMAX>
__device__ __forceinline__ void shflSweepCT(float* v, bool lo16, bool lo8,
                                            bool lo4, bool lo2, bool lo1) {
    shflStepCT<16, KR, RMAX>(v, lo16);
    shflStepCT<8,  KR, RMAX>(v, lo8);
    shflStepCT<4,  KR, RMAX>(v, lo4);
    shflStepCT<2,  KR, RMAX>(v, lo2);
    shflStepCT<1,  KR, RMAX>(v, lo1);
}
template<int JR>
__device__ __forceinline__ void mergeStepDual(float* v) {
#pragma unroll
    for (int q = 0; q < 8; q++) if (!(q & JR)) {
        { float a = v[q], b = v[q | JR];
          v[q] = fmaxf(a, b); v[q | JR] = fminf(a, b); }
        { float a = v[16 + q], b = v[16 + (q | JR)];
          v[16 + q] = fminf(a, b); v[16 + (q | JR)] = fmaxf(a, b); }
    }
}
template<int J>
__device__ __forceinline__ void shflMergeDual(float* v, bool loJ) {
#pragma unroll
    for (int q = 0; q < 8; q++) {
        { float p = __shfl_xor_sync(0xffffffffu, v[q], J);
          float mn = fminf(v[q], p), mx = fmaxf(v[q], p);
          v[q] = loJ ? mx : mn; }
        { float p = __shfl_xor_sync(0xffffffffu, v[16 + q], J);
          float mn = fminf(v[16 + q], p), mx = fmaxf(v[16 + q], p);
          v[16 + q] = loJ ? mn : mx; }
    }
}
template<int JR>
__device__ __forceinline__ void mergeStepFinal(float* v) {
#pragma unroll
    for (int q = 0; q < 8; q++) if (!(q & JR)) {
        float a = v[q], b = v[q | JR];
        v[q] = fmaxf(a, b); v[q | JR] = fminf(a, b);
    }
}
template<int J>
__device__ __forceinline__ void shflFinal(float* v, bool loJ) {
#pragma unroll
    for (int q = 0; q < 8; q++) {
        float p  = __shfl_xor_sync(0xffffffffu, v[q], J);
        float mn = fminf(v[q], p), mx = fmaxf(v[q], p);
        v[q] = loJ ? mx : mn;
    }
}

__global__ __launch_bounds__(256) void topk_warp_kernel(
    const float* __restrict__ srcQ, float* __restrict__ dstQ,
    const float* __restrict__ srcK, float* __restrict__ dstK, int nrows)
{
    const int lane = threadIdx.x & 31;
    const int row  = blockIdx.x * (blockDim.x >> 5) + (threadIdx.x >> 5);
    if (row >= nrows) return;

    const float* src = blockIdx.y ? srcK : srcQ;
    float*       dst = blockIdx.y ? dstK : dstQ;

    const float* rp = src + (size_t)row * HWD;
    float v[32];
#pragma unroll
    for (int r = 0; r < 24; r++) v[r] = rp[r * 32 + lane];
#pragma unroll
    for (int r = 24; r < 32; r++) v[r] = -CUDART_INF_F;

    {
        float t = (lane < 16) ? rp[24 * 32 + lane] : -CUDART_INF_F;
#pragma unroll
        for (int k = 2; k <= 32; k <<= 1) {
#pragma unroll
            for (int j = 16; j > 0; j >>= 1) {
                if (j < k) {
                    bool up = ((lane & k) == 0) || (k == 32);
                    float p = __shfl_xor_sync(0xffffffffu, t, j);
                    bool take_min = (((lane & j) == 0) == up);
                    float mn = fminf(t, p), mx = fmaxf(t, p);
                    t = take_min ? mn : mx;
                }
            }
        }
        v[31] = t;
    }

    const bool lo1  = (lane & 1)  == 0;
    const bool lo2  = (lane & 2)  == 0;
    const bool lo4  = (lane & 4)  == 0;
    const bool lo8  = (lane & 8)  == 0;
    const bool lo16 = (lane & 16) == 0;

    shflStepRT<1, 24>(v, lo2 == lo1);
    shflStepRT<2, 24>(v, lo4 == lo2);
    shflStepRT<1, 24>(v, lo4 == lo1);
    shflStepRT<4, 24>(v, lo8 == lo4);
    shflStepRT<2, 24>(v, lo8 == lo2);
    shflStepRT<1, 24>(v, lo8 == lo1);
    shflStepRT<8, 24>(v, lo16 == lo8);
    shflStepRT<4, 24>(v, lo16 == lo4);
    shflStepRT<2, 24>(v, lo16 == lo2);
    shflStepRT<1, 24>(v, lo16 == lo1);

    shflSweepCT<1, 24>(v, lo16, lo8, lo4, lo2, lo1);
    regStep<1, 2, 24>(v);
    shflSweepCT<2, 24>(v, lo16, lo8, lo4, lo2, lo1);
    regStep<2, 4, 24>(v); regStep<1, 4, 24>(v);
    shflSweepCT<4, 24>(v, lo16, lo8, lo4, lo2, lo1);
    regStep<4, 8, 24>(v); regStep<2, 8, 24>(v); regStep<1, 8, 24>(v);
    shflSweepCT<8, 24>(v, lo16, lo8, lo4, lo2, lo1);

#pragma unroll
    for (int q = 0; q < 8; q++) {
        { float a = v[q],      b = v[q + 8];
          v[q]      = fmaxf(a, b); v[q + 8]  = fminf(a, b); }
        { float a = v[16 + q], b = v[24 + q];
          v[16 + q] = fmaxf(a, b); v[24 + q] = fminf(a, b); }
    }
    mergeStepDual<4>(v); mergeStepDual<2>(v); mergeStepDual<1>(v);
    shflMergeDual<16>(v, lo16); shflMergeDual<8>(v, lo8);
    shflMergeDual<4>(v, lo4);   shflMergeDual<2>(v, lo2);
    shflMergeDual<1>(v, lo1);
#pragma unroll
    for (int q = 0; q < 8; q++) v[q] = fmaxf(v[q], v[16 + q]);
    mergeStepFinal<4>(v); mergeStepFinal<2>(v); mergeStepFinal<1>(v);
    shflFinal<16>(v, lo16); shflFinal<8>(v, lo8);
    shflFinal<4>(v, lo4);   shflFinal<2>(v, lo2);
    shflFinal<1>(v, lo1);

    float* dp = dst + (size_t)row * KTOP;
#pragma unroll
    for (int r = 0; r < 6; r++) dp[r * 32 + lane] = v[r];
    if (lane < 4) dp[6 * 32 + lane] = v[6];
}

// ---------------------------------------------------------------------------
// Attention. One block per n; warp w owns rows t=w, w+8 in registers.
// Hot loop vectorized: float4 V loads + float4 Y stores (HWD % 4 == 0).
// ---------------------------------------------------------------------------
__global__ __launch_bounds__(256, 4) void attn_kernel(
    const float* __restrict__ Qt, const float* __restrict__ Kt,
    const float* __restrict__ V, float* __restrict__ Y)
{
    __shared__ float sQ[TT * KTOP];
    __shared__ float sK[TT * KTOP];
    __shared__ float sA[TT * TT];

    const int n    = blockIdx.x;
    const int tid  = threadIdx.x;
    const int lane = tid & 31;
    const int wid  = tid >> 5;

    const float* qb = Qt + (long)n * TT * KTOP;
    const float* kb = Kt + (long)n * TT * KTOP;
    // float4 staging copy (TT*KTOP = 3136 floats = 784 float4)
    {
        const float4* q4 = reinterpret_cast<const float4*>(qb);
        const float4* k4 = reinterpret_cast<const float4*>(kb);
        float4* sq4 = reinterpret_cast<float4*>(sQ);
        float4* sk4 = reinterpret_cast<float4*>(sK);
        for (int i = tid; i < (TT * KTOP) / 4; i += 256) {
            sq4[i] = q4[i];
            sk4[i] = k4[i];
        }
    }
    __syncthreads();

    {
        int t = tid >> 4, s = tid & 15;
        const float4* q4 = reinterpret_cast<const float4*>(sQ + t * KTOP);
        const float4* k4 = reinterpret_cast<const float4*>(sK + s * KTOP);
        float acc = 0.f;
#pragma unroll 7
        for (int j = 0; j < KTOP / 4; j++) {
            float4 a = q4[j], b = k4[j];
            acc = fmaf(a.x, b.x, acc);
            acc = fmaf(a.y, b.y, acc);
            acc = fmaf(a.z, b.z, acc);
            acc = fmaf(a.w, b.w, acc);
        }
        sA[t * 16 + s] = acc;
    }
    __syncthreads();

    if (tid < TT) {
        int t = tid;
        float mx = -CUDART_INF_F;
#pragma unroll
        for (int s = 0; s < 16; s++) mx = fmaxf(mx, sA[t * 16 + s]);
        float sum = 0.f;
        float e[16];
#pragma unroll
        for (int s = 0; s < 16; s++) { e[s] = __expf(sA[t * 16 + s] - mx); sum += e[s]; }
        float inv = 1.f / sum;
#pragma unroll
        for (int s = 0; s < 16; s++) sA[t * 16 + s] = e[s] * inv;
    }
    __syncthreads();

    float a0r[TT], a1r[TT];
#pragma unroll
    for (int s = 0; s < TT; s++) {
        a0r[s] = sA[wid * 16 + s];
        a1r[s] = sA[(wid + 8) * 16 + s];
    }

    const float4* vb4 = reinterpret_cast<const float4*>(V + (long)n * THW);
    float4* y04 = reinterpret_cast<float4*>(Y + (long)n * THW + (long)wid * HWD);
    float4* y14 = reinterpret_cast<float4*>(Y + (long)n * THW + (long)(wid + 8) * HWD);
    const int HWD4 = HWD / 4;   // 196

#pragma unroll 1
    for (int p4 = lane; p4 < HWD4; p4 += 32) {
        float4 acc0 = make_float4(0.f, 0.f, 0.f, 0.f);
        float4 acc1 = make_float4(0.f, 0.f, 0.f, 0.f);
#pragma unroll
        for (int s = 0; s < TT; s++) {
            float4 vv = vb4[s * HWD4 + p4];
            float w0 = a0r[s], w1 = a1r[s];
            acc0.x = fmaf(w0, vv.x, acc0.x);
            acc0.y = fmaf(w0, vv.y, acc0.y);
            acc0.z = fmaf(w0, vv.z, acc0.z);
            acc0.w = fmaf(w0, vv.w, acc0.w);
            acc1.x = fmaf(w1, vv.x, acc1.x);
            acc1.y = fmaf(w1, vv.y, acc1.y);
            acc1.z = fmaf(w1, vv.z, acc1.z);
            acc1.w = fmaf(w1, vv.w, acc1.w);
        }
        y04[p4] = make_float4(f2tf32f(acc0.x), f2tf32f(acc0.y),
                              f2tf32f(acc0.z), f2tf32f(acc0.w));
        y14[p4] = make_float4(f2tf32f(acc1.x), f2tf32f(acc1.y),
                              f2tf32f(acc1.z), f2tf32f(acc1.w));
    }
}

// ---------------------------------------------------------------------------
extern "C" void kernel_launch(void* const* d_in, const int* in_sizes, int n_in,
                              void* d_out, int out_size)
{
    const float* x      = (const float*)d_in[0];
    const float* Wq     = (const float*)d_in[1];
    const float* bq     = (const float*)d_in[2];
    const float* Wk     = (const float*)d_in[3];
    const float* bk     = (const float*)d_in[4];
    const float* Wv     = (const float*)d_in[5];
    const float* bv     = (const float*)d_in[6];
    const float* Wr     = (const float*)d_in[7];
    const float* br     = (const float*)d_in[8];
    const float* gamma  = (const float*)d_in[9];
    const float* beta   = (const float*)d_in[10];
    const float* bnmean = (const float*)d_in[11];
    const float* bnvar  = (const float*)d_in[12];
    float* out = (float*)d_out;

    float *Qp, *Kp, *Vp, *Qtp, *Ktp, *Yp, *Wqt, *Wkt, *Wvt, *Wrt;
    cudaGetSymbolAddress((void**)&Qp,  g_Q);
    cudaGetSymbolAddress((void**)&Kp,  g_K);
    cudaGetSymbolAddress((void**)&Vp,  g_V);
    cudaGetSymbolAddress((void**)&Qtp, g_Qt);
    cudaGetSymbolAddress((void**)&Ktp, g_Kt);
    cudaGetSymbolAddress((void**)&Yp,  g_Y);
    cudaGetSymbolAddress((void**)&Wqt, g_Wqt);
    cudaGetSymbolAddress((void**)&Wkt, g_Wkt);
    cudaGetSymbolAddress((void**)&Wvt, g_Wvt);
    cudaGetSymbolAddress((void**)&Wrt, g_Wrt);

    dim3 gW(128, 4);
    wconv_kernel<<<gW, 256>>>(Wq, Wk, Wv, Wr, Wqt, Wkt, Wvt, Wrt);

    dim3 gQKV(3, THW / TBN, BB);             // (3, 98, 8)
    gemm_tf32_pipe_kernel<1><<<gQKV, 512>>>(
        Wqt, Wkt, Wvt, x, Qp, Kp, Vp, bq, bk, bv,
        nullptr, nullptr, nullptr, nullptr, nullptr, CR, CC, 0);

    const int nrows = NROW * TT;             // 16384
    const int wpb = 8;
    dim3 gTK((nrows + wpb - 1) / wpb, 2);
    topk_warp_kernel<<<gTK, 32 * wpb>>>(Qp, Qtp, Kp, Ktp, nrows);

    attn_kernel<<<NROW, 256>>>(Qtp, Ktp, Vp, Yp);

    dim3 gRec(CC / TBM, THW / TBN, BB);      // (2, 98, 8)
    gemm_tf32_pipe_kernel<0><<<gRec, 512>>>(
        Wrt, nullptr, nullptr, Yp, out, nullptr, nullptr, br, nullptr, nullptr,
        gamma, beta, bnmean, bnvar, x, CC, CR, 1);
}

// round 16
// speedup vs baseline: 1.2702x; 1.0030x over previous
#include <cuda_runtime.h>
#include <math_constants.h>
#include <cstdint>

// Problem constants
#define BB   8
#define CC   256
#define CR   128
#define TT   16
#define HWD  784            // 28*28
#define THW  12544          // 16*784
#define KTOP 196            // 784/4
#define NROW 1024           // B*CR
#define BN_EPS 1e-5f

// Scratch buffers
__device__ float g_Q [BB * CR * THW];
__device__ float g_K [BB * CR * THW];
__device__ float g_V [BB * CR * THW];
__device__ float g_Qt[NROW * TT * KTOP];
__device__ float g_Kt[NROW * TT * KTOP];
__device__ float g_Y [BB * CR * THW];
// Pre-converted (tf32-bit) weights
__device__ float g_Wqt[CR * CC];
__device__ float g_Wkt[CR * CC];
__device__ float g_Wvt[CR * CC];
__device__ float g_Wrt[CC * CR];

__device__ __forceinline__ uint32_t f2tf32(float x) {
    uint32_t u;
    asm("cvt.rna.tf32.f32 %0, %1;" : "=r"(u) : "f"(x));
    return u;
}
__device__ __forceinline__ float f2tf32f(float x) {
    return __uint_as_float(f2tf32(x));
}
__device__ __forceinline__ void cpasync16(uint32_t daddr, const void* src) {
    asm volatile("cp.async.ca.shared.global [%0], [%1], 16;\n"
                 :: "r"(daddr), "l"(src));
}

// ---------------------------------------------------------------------------
// Weight tf32 preconversion
// ---------------------------------------------------------------------------
__global__ __launch_bounds__(256) void wconv_kernel(
    const float* __restrict__ w0, const float* __restrict__ w1,
    const float* __restrict__ w2, const float* __restrict__ w3,
    float* __restrict__ d0, float* __restrict__ d1,
    float* __restrict__ d2, float* __restrict__ d3)
{
    const int a = blockIdx.y;
    const float* s = (a == 0) ? w0 : (a == 1) ? w1 : (a == 2) ? w2 : w3;
    float*       d = (a == 0) ? d0 : (a == 1) ? d1 : (a == 2) ? d2 : d3;
    int i = blockIdx.x * 256 + threadIdx.x;
    d[i] = __uint_as_float(f2tf32(s[i]));
}

// ---------------------------------------------------------------------------
// Pipelined tf32 GEMM, 2-stage cp.async, 512 threads (16 warps, 4Mx4N).
// ---------------------------------------------------------------------------
#define TBM 128
#define TBN 128
#define TBK 16
#define APAD 20
#define BPAD 136

template<int CVTB>
__global__ __launch_bounds__(512) void gemm_tf32_pipe_kernel(
    const float* __restrict__ A0, const float* __restrict__ A1,
    const float* __restrict__ A2,
    const float* __restrict__ Bmat,
    float* __restrict__ C0, float* __restrict__ C1, float* __restrict__ C2,
    const float* __restrict__ bias0, const float* __restrict__ bias1,
    const float* __restrict__ bias2,
    const float* __restrict__ gamma,
    const float* __restrict__ beta,
    const float* __restrict__ bn_mean,
    const float* __restrict__ bn_var,
    const float* __restrict__ xres,
    int M, int K, int mode)
{
    const int b    = blockIdx.z;
    const int bx   = blockIdx.x;
    const int n0   = blockIdx.y * TBN;
    const int tid  = threadIdx.x;
    const int lane = tid & 31;
    const int wid  = tid >> 5;
    const int wm   = wid >> 2;
    const int wn   = wid & 3;

    const float* A;
    const float* bias;
    float* C;
    int m0;
    if (mode == 0) {
        A    = (bx == 0) ? A0 : (bx == 1) ? A1 : A2;
        bias = (bx == 0) ? bias0 : (bx == 1) ? bias1 : bias2;
        C    = (bx == 0) ? C0 : (bx == 1) ? C1 : C2;
        m0   = 0;
    } else {
        A = A0; bias = bias0; C = C0;
        m0 = bx * TBM;
    }

    const float* Bb = Bmat + (size_t)b * K * THW;
    float*       Cb = C    + (size_t)b * M * THW;

    __shared__ float As[2][TBM][APAD];
    __shared__ float Bs[2][TBK][BPAD];

    float acc[2][4][4];
#pragma unroll
    for (int i = 0; i < 2; i++)
#pragma unroll
        for (int j = 0; j < 4; j++)
#pragma unroll
            for (int q = 0; q < 4; q++) acc[i][j][q] = 0.f;

    const int row = lane >> 2;
    const int kc  = lane & 3;

    const int am = tid >> 2, ak = tid & 3;
    const int bk = tid >> 5, bn = tid & 31;

    uint32_t asBase = (uint32_t)__cvta_generic_to_shared(&As[0][0][0]);
    uint32_t bsBase = (uint32_t)__cvta_generic_to_shared(&Bs[0][0][0]);
    const uint32_t asStage = TBM * APAD * 4;
    const uint32_t bsStage = TBK * BPAD * 4;

    const int nkt = K / TBK;

    cpasync16(asBase + (am * APAD + ak * 4) * 4,
              A + (size_t)(m0 + am) * K + ak * 4);
    cpasync16(bsBase + (bk * BPAD + bn * 4) * 4,
              Bb + (size_t)bk * THW + n0 + bn * 4);
    asm volatile("cp.async.commit_group;\n");

    for (int i = 0; i < nkt; i++) {
        const int s = i & 1;
        if (i + 1 < nkt) {
            const int kt = (i + 1) * TBK;
            const uint32_t so = (s ^ 1);
            cpasync16(asBase + so * asStage + (am * APAD + ak * 4) * 4,
                      A + (size_t)(m0 + am) * K + kt + ak * 4);
            cpasync16(bsBase + so * bsStage + (bk * BPAD + bn * 4) * 4,
                      Bb + (size_t)(kt + bk) * THW + n0 + bn * 4);
            asm volatile("cp.async.commit_group;\n");
            asm volatile("cp.async.wait_group 1;\n");
        } else {
            asm volatile("cp.async.wait_group 0;\n");
        }
        __syncthreads();

#pragma unroll
        for (int ks = 0; ks < 2; ks++) {
            const int kb = ks * 8;
            uint32_t af[2][4];
#pragma unroll
            for (int mt = 0; mt < 2; mt++) {
                int mr = wm * 32 + mt * 16 + row;
                af[mt][0] = __float_as_uint(As[s][mr    ][kb + kc    ]);
                af[mt][1] = __float_as_uint(As[s][mr + 8][kb + kc    ]);
                af[mt][2] = __float_as_uint(As[s][mr    ][kb + kc + 4]);
                af[mt][3] = __float_as_uint(As[s][mr + 8][kb + kc + 4]);
            }
            uint32_t bf[4][2];
#pragma unroll
            for (int nt = 0; nt < 4; nt++) {
                int nc = wn * 32 + nt * 8 + row;
                if (CVTB) {
                    bf[nt][0] = f2tf32(Bs[s][kb + kc    ][nc]);
                    bf[nt][1] = f2tf32(Bs[s][kb + kc + 4][nc]);
                } else {
                    bf[nt][0] = __float_as_uint(Bs[s][kb + kc    ][nc]);
                    bf[nt][1] = __float_as_uint(Bs[s][kb + kc + 4][nc]);
                }
            }
#pragma unroll
            for (int mt = 0; mt < 2; mt++)
#pragma unroll
                for (int nt = 0; nt < 4; nt++) {
                    asm volatile(
                        "mma.sync.aligned.m16n8k8.row.col.f32.tf32.tf32.f32 "
                        "{%0,%1,%2,%3}, {%4,%5,%6,%7}, {%8,%9}, {%0,%1,%2,%3};"
                        : "+f"(acc[mt][nt][0]), "+f"(acc[mt][nt][1]),
                          "+f"(acc[mt][nt][2]), "+f"(acc[mt][nt][3])
                        : "r"(af[mt][0]), "r"(af[mt][1]),
                          "r"(af[mt][2]), "r"(af[mt][3]),
                          "r"(bf[nt][0]), "r"(bf[nt][1]));
                }
        }
        __syncthreads();
    }

    const int coln = 2 * (lane & 3);
#pragma unroll
    for (int mt = 0; mt < 2; mt++) {
#pragma unroll
        for (int half = 0; half < 2; half++) {
            int m = m0 + wm * 32 + mt * 16 + row + half * 8;
            float bi = bias[m];
            float sc = 1.f, sh = 0.f;
            if (mode == 1) {
                sc = gamma[m] * rsqrtf(bn_var[m] + BN_EPS);
                sh = beta[m] - bn_mean[m] * sc;
            }
#pragma unroll
            for (int nt = 0; nt < 4; nt++) {
                int n = n0 + wn * 32 + nt * 8 + coln;
                float v0 = acc[mt][nt][half * 2 + 0] + bi;
                float v1 = acc[mt][nt][half * 2 + 1] + bi;
                if (mode == 1) {
                    const float* xr = xres + (size_t)b * CC * THW + (size_t)m * THW + n;
                    v0 = v0 * sc + sh + xr[0];
                    v1 = v1 * sc + sh + xr[1];
                }
                *reinterpret_cast<float2*>(&Cb[(size_t)m * THW + n]) =
                    make_float2(v0, v1);
            }
        }
    }
}

// ---------------------------------------------------------------------------
// Pruned warp top-k (unchanged — known good)
// ---------------------------------------------------------------------------
template<int J, int RMAX>
__device__ __forceinline__ void shflStepRT(float* v, bool tm) {
#pragma unroll
    for (int r = 0; r < RMAX; r++) {
        float p  = __shfl_xor_sync(0xffffffffu, v[r], J);
        float mn = fminf(v[r], p), mx = fmaxf(v[r], p);
        v[r] = tm ? mx : mn;
    }
}
template<int J, int KR, int RMAX>
__device__ __forceinline__ void shflStepCT(float* v, bool loJ) {
#pragma unroll
    for (int r = 0; r < RMAX; r++) {
        const bool tm = ((r & KR) == 0) ? true : false;
        float p  = __shfl_xor_sync(0xffffffffu, v[r], J);
        float mn = fminf(v[r], p), mx = fmaxf(v[r], p);
        v[r] = (tm ? loJ : !loJ) ? mx : mn;
    }
}
template<int JR, int KR, int RMAX>
__device__ __forceinline__ void regStep(float* v) {
#pragma unroll
    for (int r = 0; r < RMAX; r++) if (!(r & JR)) {
        float a = v[r], b = v[r | JR];
        if ((r & KR) == 0) { v[r] = fmaxf(a, b); v[r | JR] = fminf(a, b); }
        else               { v[r] = fminf(a, b); v[r | JR] = fmaxf(a, b); }
    }
}
template<int KR, int RMAX>
__device__ __forceinline__ void shflSweepCT(float* v, bool lo16, bool lo8,
                                            bool lo4, bool lo2, bool lo1) {
    shflStepCT<16, KR, RMAX>(v, lo16);
    shflStepCT<8,  KR, RMAX>(v, lo8);
    shflStepCT<4,  KR, RMAX>(v, lo4);
    shflStepCT<2,  KR, RMAX>(v, lo2);
    shflStepCT<1,  KR, RMAX>(v, lo1);
}
template<int JR>
__device__ __forceinline__ void mergeStepDual(float* v) {
#pragma unroll
    for (int q = 0; q < 8; q++) if (!(q & JR)) {
        { float a = v[q], b = v[q | JR];
          v[q] = fmaxf(a, b); v[q | JR] = fminf(a, b); }
        { float a = v[16 + q], b = v[16 + (q | JR)];
          v[16 + q] = fminf(a, b); v[16 + (q | JR)] = fmaxf(a, b); }
    }
}
template<int J>
__device__ __forceinline__ void shflMergeDual(float* v, bool loJ) {
#pragma unroll
    for (int q = 0; q < 8; q++) {
        { float p = __shfl_xor_sync(0xffffffffu, v[q], J);
          float mn = fminf(v[q], p), mx = fmaxf(v[q], p);
          v[q] = loJ ? mx : mn; }
        { float p = __shfl_xor_sync(0xffffffffu, v[16 + q], J);
          float mn = fminf(v[16 + q], p), mx = fmaxf(v[16 + q], p);
          v[16 + q] = loJ ? mn : mx; }
    }
}
template<int JR>
__device__ __forceinline__ void mergeStepFinal(float* v) {
#pragma unroll
    for (int q = 0; q < 8; q++) if (!(q & JR)) {
        float a = v[q], b = v[q | JR];
        v[q] = fmaxf(a, b); v[q | JR] = fminf(a, b);
    }
}
template<int J>
__device__ __forceinline__ void shflFinal(float* v, bool loJ) {
#pragma unroll
    for (int q = 0; q < 8; q++) {
        float p  = __shfl_xor_sync(0xffffffffu, v[q], J);
        float mn = fminf(v[q], p), mx = fmaxf(v[q], p);
        v[q] = loJ ? mx : mn;
    }
}

__global__ __launch_bounds__(256) void topk_warp_kernel(
    const float* __restrict__ srcQ, float* __restrict__ dstQ,
    const float* __restrict__ srcK, float* __restrict__ dstK, int nrows)
{
    const int lane = threadIdx.x & 31;
    const int row  = blockIdx.x * (blockDim.x >> 5) + (threadIdx.x >> 5);
    if (row >= nrows) return;

    const float* src = blockIdx.y ? srcK : srcQ;
    float*       dst = blockIdx.y ? dstK : dstQ;

    const float* rp = src + (size_t)row * HWD;
    float v[32];
#pragma unroll
    for (int r = 0; r < 24; r++) v[r] = rp[r * 32 + lane];
#pragma unroll
    for (int r = 24; r < 32; r++) v[r] = -CUDART_INF_F;

    {
        float t = (lane < 16) ? rp[24 * 32 + lane] : -CUDART_INF_F;
#pragma unroll
        for (int k = 2; k <= 32; k <<= 1) {
#pragma unroll
            for (int j = 16; j > 0; j >>= 1) {
                if (j < k) {
                    bool up = ((lane & k) == 0) || (k == 32);
                    float p = __shfl_xor_sync(0xffffffffu, t, j);
                    bool take_min = (((lane & j) == 0) == up);
                    float mn = fminf(t, p), mx = fmaxf(t, p);
                    t = take_min ? mn : mx;
                }
            }
        }
        v[31] = t;
    }

    const bool lo1  = (lane & 1)  == 0;
    const bool lo2  = (lane & 2)  == 0;
    const bool lo4  = (lane & 4)  == 0;
    const bool lo8  = (lane & 8)  == 0;
    const bool lo16 = (lane & 16) == 0;

    shflStepRT<1, 24>(v, lo2 == lo1);
    shflStepRT<2, 24>(v, lo4 == lo2);
    shflStepRT<1, 24>(v, lo4 == lo1);
    shflStepRT<4, 24>(v, lo8 == lo4);
    shflStepRT<2, 24>(v, lo8 == lo2);
    shflStepRT<1, 24>(v, lo8 == lo1);
    shflStepRT<8, 24>(v, lo16 == lo8);
    shflStepRT<4, 24>(v, lo16 == lo4);
    shflStepRT<2, 24>(v, lo16 == lo2);
    shflStepRT<1, 24>(v, lo16 == lo1);

    shflSweepCT<1, 24>(v, lo16, lo8, lo4, lo2, lo1);
    regStep<1, 2, 24>(v);
    shflSweepCT<2, 24>(v, lo16, lo8, lo4, lo2, lo1);
    regStep<2, 4, 24>(v); regStep<1, 4, 24>(v);
    shflSweepCT<4, 24>(v, lo16, lo8, lo4, lo2, lo1);
    regStep<4, 8, 24>(v); regStep<2, 8, 24>(v); regStep<1, 8, 24>(v);
    shflSweepCT<8, 24>(v, lo16, lo8, lo4, lo2, lo1);

#pragma unroll
    for (int q = 0; q < 8; q++) {
        { float a = v[q],      b = v[q + 8];
          v[q]      = fmaxf(a, b); v[q + 8]  = fminf(a, b); }
        { float a = v[16 + q], b = v[24 + q];
          v[16 + q] = fmaxf(a, b); v[24 + q] = fminf(a, b); }
    }
    mergeStepDual<4>(v); mergeStepDual<2>(v); mergeStepDual<1>(v);
    shflMergeDual<16>(v, lo16); shflMergeDual<8>(v, lo8);
    shflMergeDual<4>(v, lo4);   shflMergeDual<2>(v, lo2);
    shflMergeDual<1>(v, lo1);
#pragma unroll
    for (int q = 0; q < 8; q++) v[q] = fmaxf(v[q], v[16 + q]);
    mergeStepFinal<4>(v); mergeStepFinal<2>(v); mergeStepFinal<1>(v);
    shflFinal<16>(v, lo16); shflFinal<8>(v, lo8);
    shflFinal<4>(v, lo4);   shflFinal<2>(v, lo2);
    shflFinal<1>(v, lo1);

    float* dp = dst + (size_t)row * KTOP;
#pragma unroll
    for (int r = 0; r < 6; r++) dp[r * 32 + lane] = v[r];
    if (lane < 4) dp[6 * 32 + lane] = v[6];
}

// ---------------------------------------------------------------------------
// Attention (unchanged from R14 — known good)
// ---------------------------------------------------------------------------
__global__ __launch_bounds__(256, 4) void attn_kernel(
    const float* __restrict__ Qt, const float* __restrict__ Kt,
    const float* __restrict__ V, float* __restrict__ Y)
{
    __shared__ float sQ[TT * KTOP];
    __shared__ float sK[TT * KTOP];
    __shared__ float sA[TT * TT];

    const int n    = blockIdx.x;
    const int tid  = threadIdx.x;
    const int lane = tid & 31;
    const int wid  = tid >> 5;

    const float* qb = Qt + (long)n * TT * KTOP;
    const float* kb = Kt + (long)n * TT * KTOP;
    {
        const float4* q4 = reinterpret_cast<const float4*>(qb);
        const float4* k4 = reinterpret_cast<const float4*>(kb);
        float4* sq4 = reinterpret_cast<float4*>(sQ);
        float4* sk4 = reinterpret_cast<float4*>(sK);
        for (int i = tid; i < (TT * KTOP) / 4; i += 256) {
            sq4[i] = q4[i];
            sk4[i] = k4[i];
        }
    }
    __syncthreads();

    {
        int t = tid >> 4, s = tid & 15;
        const float4* q4 = reinterpret_cast<const float4*>(sQ + t * KTOP);
        const float4* k4 = reinterpret_cast<const float4*>(sK + s * KTOP);
        float acc = 0.f;
#pragma unroll 7
        for (int j = 0; j < KTOP / 4; j++) {
            float4 a = q4[j], b = k4[j];
            acc = fmaf(a.x, b.x, acc);
            acc = fmaf(a.y, b.y, acc);
            acc = fmaf(a.z, b.z, acc);
            acc = fmaf(a.w, b.w, acc);
        }
        sA[t * 16 + s] = acc;
    }
    __syncthreads();

    if (tid < TT) {
        int t = tid;
        float mx = -CUDART_INF_F;
#pragma unroll
        for (int s = 0; s < 16; s++) mx = fmaxf(mx, sA[t * 16 + s]);
        float sum = 0.f;
        float e[16];
#pragma unroll
        for (int s = 0; s < 16; s++) { e[s] = __expf(sA[t * 16 + s] - mx); sum += e[s]; }
        float inv = 1.f / sum;
#pragma unroll
        for (int s = 0; s < 16; s++) sA[t * 16 + s] = e[s] * inv;
    }
    __syncthreads();

    float a0r[TT], a1r[TT];
#pragma unroll
    for (int s = 0; s < TT; s++) {
        a0r[s] = sA[wid * 16 + s];
        a1r[s] = sA[(wid + 8) * 16 + s];
    }

    const float4* vb4 = reinterpret_cast<const float4*>(V + (long)n * THW);
    float4* y04 = reinterpret_cast<float4*>(Y + (long)n * THW + (long)wid * HWD);
    float4* y14 = reinterpret_cast<float4*>(Y + (long)n * THW + (long)(wid + 8) * HWD);
    const int HWD4 = HWD / 4;   // 196

#pragma unroll 1
    for (int p4 = lane; p4 < HWD4; p4 += 32) {
        float4 acc0 = make_float4(0.f, 0.f, 0.f, 0.f);
        float4 acc1 = make_float4(0.f, 0.f, 0.f, 0.f);
#pragma unroll
        for (int s = 0; s < TT; s++) {
            float4 vv = vb4[s * HWD4 + p4];
            float w0 = a0r[s], w1 = a1r[s];
            acc0.x = fmaf(w0, vv.x, acc0.x);
            acc0.y = fmaf(w0, vv.y, acc0.y);
            acc0.z = fmaf(w0, vv.z, acc0.z);
            acc0.w = fmaf(w0, vv.w, acc0.w);
            acc1.x = fmaf(w1, vv.x, acc1.x);
            acc1.y = fmaf(w1, vv.y, acc1.y);
            acc1.z = fmaf(w1, vv.z, acc1.z);
            acc1.w = fmaf(w1, vv.w, acc1.w);
        }
        y04[p4] = make_float4(f2tf32f(acc0.x), f2tf32f(acc0.y),
                              f2tf32f(acc0.z), f2tf32f(acc0.w));
        y14[p4] = make_float4(f2tf32f(acc1.x), f2tf32f(acc1.y),
                              f2tf32f(acc1.z), f2tf32f(acc1.w));
    }
}

// ---------------------------------------------------------------------------
// Launcher with capture-forked stream: V-GEMM runs concurrently with topk.
// Dependency graph: wconv -> {QK-GEMM -> topk (s0)}, {V-GEMM (s1)} -> attn -> rec
// ---------------------------------------------------------------------------
extern "C" void kernel_launch(void* const* d_in, const int* in_sizes, int n_in,
                              void* d_out, int out_size)
{
    const float* x      = (const float*)d_in[0];
    const float* Wq     = (const float*)d_in[1];
    const float* bq     = (const float*)d_in[2];
    const float* Wk     = (const float*)d_in[3];
    const float* bk     = (const float*)d_in[4];
    const float* Wv     = (const float*)d_in[5];
    const float* bv     = (const float*)d_in[6];
    const float* Wr     = (const float*)d_in[7];
    const float* br     = (const float*)d_in[8];
    const float* gamma  = (const float*)d_in[9];
    const float* beta   = (const float*)d_in[10];
    const float* bnmean = (const float*)d_in[11];
    const float* bnvar  = (const float*)d_in[12];
    float* out = (float*)d_out;

    float *Qp, *Kp, *Vp, *Qtp, *Ktp, *Yp, *Wqt, *Wkt, *Wvt, *Wrt;
    cudaGetSymbolAddress((void**)&Qp,  g_Q);
    cudaGetSymbolAddress((void**)&Kp,  g_K);
    cudaGetSymbolAddress((void**)&Vp,  g_V);
    cudaGetSymbolAddress((void**)&Qtp, g_Qt);
    cudaGetSymbolAddress((void**)&Ktp, g_Kt);
    cudaGetSymbolAddress((void**)&Yp,  g_Y);
    cudaGetSymbolAddress((void**)&Wqt, g_Wqt);
    cudaGetSymbolAddress((void**)&Wkt, g_Wkt);
    cudaGetSymbolAddress((void**)&Wvt, g_Wvt);
    cudaGetSymbolAddress((void**)&Wrt, g_Wrt);

    cudaStream_t s1;
    cudaStreamCreateWithFlags(&s1, cudaStreamNonBlocking);
    cudaEvent_t evW, evV;
    cudaEventCreateWithFlags(&evW, cudaEventDisableTiming);
    cudaEventCreateWithFlags(&evV, cudaEventDisableTiming);

    // s0: weight preconversion (QK-GEMM and V-GEMM both depend on it)
    dim3 gW(128, 4);
    wconv_kernel<<<gW, 256>>>(Wq, Wk, Wv, Wr, Wqt, Wkt, Wvt, Wrt);
    cudaEventRecord(evW, 0);

    // s1: V-GEMM (independent of Q/K downstream work)
    cudaStreamWaitEvent(s1, evW, 0);
    dim3 gV(1, THW / TBN, BB);               // (1, 98, 8) — bx==0 selects slot 0
    gemm_tf32_pipe_kernel<1><<<gV, 512, 0, s1>>>(
        Wvt, nullptr, nullptr, x, Vp, nullptr, nullptr, bv, nullptr, nullptr,
        nullptr, nullptr, nullptr, nullptr, nullptr, CR, CC, 0);
    cudaEventRecord(evV, s1);

    // s0: Q+K GEMM (grid.x = 2 covers Q,K), then topk — concurrent with V-GEMM
    dim3 gQK(2, THW / TBN, BB);              // (2, 98, 8)
    gemm_tf32_pipe_kernel<1><<<gQK, 512>>>(
        Wqt, Wkt, Wvt, x, Qp, Kp, Vp, bq, bk, bv,
        nullptr, nullptr, nullptr, nullptr, nullptr, CR, CC, 0);

    const int nrows = NROW * TT;             // 16384
    const int wpb = 8;
    dim3 gTK((nrows + wpb - 1) / wpb, 2);
    topk_warp_kernel<<<gTK, 32 * wpb>>>(Qp, Qtp, Kp, Ktp, nrows);

    // join: attn needs V (s1) + Qt/Kt (s0)
    cudaStreamWaitEvent(0, evV, 0);
    attn_kernel<<<NROW, 256>>>(Qtp, Ktp, Vp, Yp);

    dim3 gRec(CC / TBM, THW / TBN, BB);      // (2, 98, 8)
    gemm_tf32_pipe_kernel<0><<<gRec, 512>>>(
        Wrt, nullptr, nullptr, Yp, out, nullptr, nullptr, br, nullptr, nullptr,
        gamma, beta, bnmean, bnvar, x, CC, CR, 1);

    cudaEventDestroy(evW);
    cudaEventDestroy(evV);
    cudaStreamDestroy(s1);
}